// round 5
// baseline (speedup 1.0000x reference)
#include <cuda_runtime.h>
#include <cuda_bf16.h>
#include <cstdint>
#include <cstddef>

namespace {

constexpr int Nc = 16384, Kc = 32, Dc = 64;
constexpr int POINTS = 4 * Nc;           // 65536
constexpr int NTHR   = 128;              // 4 warps / CTA
constexpr int NCTA   = 444;              // 3 CTAs / SM

// ---- shared memory layout (byte offsets) ----
constexpr int SM_BFRAG = 0;              // B'' interleaved table: 4*8*32*16 = 16384 B
constexpr int SM_WARP  = 16384;          // 4 per-warp regions
constexpr int PW       = 9472;           // per-warp: H [32x256B] / Gs [32x288B] overlay
constexpr int SMEM_BYTES = SM_WARP + 4 * PW;   // 54272

__device__ __forceinline__ uint32_t smem_u32(const void* p) {
    uint32_t a;
    asm("{ .reg .u64 t; cvta.to.shared.u64 t, %1; cvt.u32.u64 %0, t; }" : "=r"(a) : "l"(p));
    return a;
}
__device__ __forceinline__ uint32_t prmt_hi(uint32_t u0, uint32_t u1) {
    uint32_t d;  // low16 = top16(u0), high16 = top16(u1)
    asm("prmt.b32 %0, %1, %2, 0x7632;" : "=r"(d) : "r"(u0), "r"(u1));
    return d;
}
__device__ __forceinline__ uint32_t cvt_bf16x2(float hi_val, float lo_val) {
    uint32_t d;  // packs {upper = hi_val, lower = lo_val}
    asm("cvt.rn.bf16x2.f32 %0, %1, %2;" : "=r"(d) : "f"(hi_val), "f"(lo_val));
    return d;
}
__device__ __forceinline__ void mma_bf16(float* c, const uint32_t* a,
                                         uint32_t b0, uint32_t b1) {
    asm volatile(
        "mma.sync.aligned.m16n8k16.row.col.f32.bf16.bf16.f32 "
        "{%0,%1,%2,%3}, {%4,%5,%6,%7}, {%8,%9}, {%0,%1,%2,%3};"
        : "+f"(c[0]), "+f"(c[1]), "+f"(c[2]), "+f"(c[3])
        : "r"(a[0]), "r"(a[1]), "r"(a[2]), "r"(a[3]), "r"(b0), "r"(b1));
}

} // namespace

// W1 (3x64) and b1 (64) — loop-invariant, uniform access -> constant port,
// keeping these 64 loads/point off the L1/shared crossbar.
__constant__ float W1c[3 * 64];
__constant__ float B1c[64];

__global__ void __launch_bounds__(NTHR, 3) pc_mma_kernel(
    const float* __restrict__ x,      // [B, N, 64]
    const float* __restrict__ pos,    // [B, N, 3]
    const int*   __restrict__ nidx,   // [B, N, 32]
    const float* __restrict__ W2,     // [64, 64]  (g-major: W2[g*64+f])
    const float* __restrict__ b2,     // [64]
    float*       __restrict__ out)    // [B, N, 64]
{
    extern __shared__ char smem[];
    const uint32_t sb = smem_u32(smem);

    const int tid  = threadIdx.x;
    const int warp = tid >> 5;
    const int lane = tid & 31;
    const int f0   = 2 * lane;

    // ================= one-time init: interleaved B'' table =================
    // entry (s, ni, ln), 16 bytes: {hi0, hi1, lo0, lo1}
    //   n  = ni*8 + (ln>>2),  k0 = s*16 + (ln&3)*2
    //   hi0 = {Bhi[k0][n], Bhi[k0+1][n]}, hi1 = {Bhi[k0+8][n], Bhi[k0+9][n]}
    for (int i = tid; i < 4 * 8 * 32; i += NTHR) {
        const int s = i >> 8, ni = (i >> 5) & 7, ln = i & 31;
        const int n  = ni * 8 + (ln >> 2);
        const int k0 = s * 16 + (ln & 3) * 2;
        const float v0 = W2[k0 * Dc + n],       v1 = W2[(k0 + 1) * Dc + n];
        const float v2 = W2[(k0 + 8) * Dc + n], v3 = W2[(k0 + 9) * Dc + n];
        const uint32_t u0 = __float_as_uint(v0), u1 = __float_as_uint(v1);
        const uint32_t u2 = __float_as_uint(v2), u3 = __float_as_uint(v3);
        uint4 e;
        e.x = (u0 >> 16) | (u1 & 0xFFFF0000u);
        e.y = (u2 >> 16) | (u3 & 0xFFFF0000u);
        const float l0 = v0 - __uint_as_float(u0 & 0xFFFF0000u);
        const float l1 = v1 - __uint_as_float(u1 & 0xFFFF0000u);
        const float l2 = v2 - __uint_as_float(u2 & 0xFFFF0000u);
        const float l3 = v3 - __uint_as_float(u3 & 0xFFFF0000u);
        e.z = cvt_bf16x2(l1, l0);
        e.w = cvt_bf16x2(l3, l2);
        *(uint4*)(smem + SM_BFRAG + (size_t)i * 16) = e;
    }
    __syncthreads();

    // ================= per-lane constants =================
    const float b20 = b2[f0], b21 = b2[f0 + 1];
    char* const wb = smem + SM_WARP + warp * PW;
    const uint32_t wbase = sb + SM_WARP + warp * PW;

    const int rl  = lane & 7;            // swizzle key (= target row & 7)
    const int grp = lane >> 3;
    const int a_row = rl + (grp & 1) * 8;
    const int csel  = grp >> 1;
    const uint32_t a_addr0 = wbase + (uint32_t)a_row * 256u;
    const uint32_t a_addr1 = wbase + (uint32_t)(a_row + 16) * 256u;
    const uint32_t bfrag_base = sb + SM_BFRAG + (uint32_t)lane * 16u;
    const int g = lane >> 2, t = lane & 3;

    // ================= per-point loop (one warp = one point) =================
    for (int p = blockIdx.x * 4 + warp; p < POINTS; p += NCTA * 4) {
        const int b = p >> 14;
        const int j = nidx[(size_t)p * Kc + lane];

        const float cx = pos[(size_t)p * 3 + 0];
        const float cy = pos[(size_t)p * 3 + 1];
        const float cz = pos[(size_t)p * 3 + 2];
        const float* npp = pos + (size_t)(b * Nc + j) * 3;
        const float rx = cx - npp[0], ry = cy - npp[1], rz = cz - npp[2];

        // ---- H build: lane = row k; hi chunks 0-7, lo chunks 8-15, swizzled ----
        {
            const uint32_t hrow = wbase + (uint32_t)lane * 256u;
#pragma unroll
            for (int c8 = 0; c8 < 8; ++c8) {
                uint32_t hq[4], lq[4];
#pragma unroll
                for (int h = 0; h < 2; ++h) {
                    const int g0 = c8 * 8 + h * 4;
                    const float4 a0 = *(const float4*)(W1c + g0);
                    const float4 a1 = *(const float4*)(W1c + Dc + g0);
                    const float4 a2 = *(const float4*)(W1c + 2 * Dc + g0);
                    const float4 bb = *(const float4*)(B1c + g0);
                    float z0 = fmaf(rx, a0.x, fmaf(ry, a1.x, fmaf(rz, a2.x, bb.x)));
                    float z1 = fmaf(rx, a0.y, fmaf(ry, a1.y, fmaf(rz, a2.y, bb.y)));
                    float z2 = fmaf(rx, a0.z, fmaf(ry, a1.z, fmaf(rz, a2.z, bb.z)));
                    float z3 = fmaf(rx, a0.w, fmaf(ry, a1.w, fmaf(rz, a2.w, bb.w)));
                    z0 = fmaxf(z0, 0.1f * z0);
                    z1 = fmaxf(z1, 0.1f * z1);
                    z2 = fmaxf(z2, 0.1f * z2);
                    z3 = fmaxf(z3, 0.1f * z3);
                    const uint32_t u0 = __float_as_uint(z0), u1 = __float_as_uint(z1);
                    const uint32_t u2 = __float_as_uint(z2), u3 = __float_as_uint(z3);
                    hq[2 * h]     = prmt_hi(u0, u1);
                    hq[2 * h + 1] = prmt_hi(u2, u3);
                    const float l0 = z0 - __uint_as_float(u0 & 0xFFFF0000u);
                    const float l1 = z1 - __uint_as_float(u1 & 0xFFFF0000u);
                    const float l2 = z2 - __uint_as_float(u2 & 0xFFFF0000u);
                    const float l3 = z3 - __uint_as_float(u3 & 0xFFFF0000u);
                    lq[2 * h]     = cvt_bf16x2(l1, l0);
                    lq[2 * h + 1] = cvt_bf16x2(l3, l2);
                }
                const uint32_t pc = (uint32_t)(c8 ^ rl);
                asm volatile("st.shared.v4.b32 [%0], {%1,%2,%3,%4};" ::
                             "r"(hrow + (pc << 4)),
                             "r"(hq[0]), "r"(hq[1]), "r"(hq[2]), "r"(hq[3]));
                asm volatile("st.shared.v4.b32 [%0], {%1,%2,%3,%4};" ::
                             "r"(hrow + ((8u + pc) << 4)),
                             "r"(lq[0]), "r"(lq[1]), "r"(lq[2]), "r"(lq[3]));
            }
        }
        __syncwarp();

        // ---- GEMM: G[32x64] = A''[32x192] * B''[192x64] ----
        float acc[64];
#pragma unroll
        for (int i = 0; i < 64; ++i) acc[i] = 0.0f;

        // pass 1: A-hi read ONCE, used against both Bhi[s] and Blo[s]
#pragma unroll
        for (int s = 0; s < 4; ++s) {
            const uint32_t cl = (uint32_t)s * 2u + (uint32_t)csel;
            const uint32_t coff = ((cl ^ (uint32_t)rl) << 4);
            uint32_t a0[4], a1[4];
            asm volatile("ldmatrix.sync.aligned.m8n8.x4.shared.b16 {%0,%1,%2,%3}, [%4];"
                         : "=r"(a0[0]), "=r"(a0[1]), "=r"(a0[2]), "=r"(a0[3])
                         : "r"(a_addr0 + coff));
            asm volatile("ldmatrix.sync.aligned.m8n8.x4.shared.b16 {%0,%1,%2,%3}, [%4];"
                         : "=r"(a1[0]), "=r"(a1[1]), "=r"(a1[2]), "=r"(a1[3])
                         : "r"(a_addr1 + coff));
            const uint32_t bptr = bfrag_base + (uint32_t)s * 4096u;
#pragma unroll
            for (int ni = 0; ni < 8; ++ni) {
                uint32_t h0, h1, l0, l1;
                asm volatile("ld.shared.v4.u32 {%0,%1,%2,%3}, [%4];"
                             : "=r"(h0), "=r"(h1), "=r"(l0), "=r"(l1)
                             : "r"(bptr + ni * 512u));
                mma_bf16(&acc[ni * 8],     a0, h0, h1);
                mma_bf16(&acc[ni * 8 + 4], a1, h0, h1);
                mma_bf16(&acc[ni * 8],     a0, l0, l1);
                mma_bf16(&acc[ni * 8 + 4], a1, l0, l1);
            }
        }
        // pass 2: A-lo against Bhi[s]
#pragma unroll
        for (int s = 0; s < 4; ++s) {
            const uint32_t cl = 8u + (uint32_t)s * 2u + (uint32_t)csel;
            const uint32_t coff = ((cl ^ (uint32_t)rl) << 4);
            uint32_t a0[4], a1[4];
            asm volatile("ldmatrix.sync.aligned.m8n8.x4.shared.b16 {%0,%1,%2,%3}, [%4];"
                         : "=r"(a0[0]), "=r"(a0[1]), "=r"(a0[2]), "=r"(a0[3])
                         : "r"(a_addr0 + coff));
            asm volatile("ldmatrix.sync.aligned.m8n8.x4.shared.b16 {%0,%1,%2,%3}, [%4];"
                         : "=r"(a1[0]), "=r"(a1[1]), "=r"(a1[2]), "=r"(a1[3])
                         : "r"(a_addr1 + coff));
            const uint32_t bptr = bfrag_base + (uint32_t)s * 4096u;
#pragma unroll
            for (int ni = 0; ni < 8; ++ni) {
                uint32_t h0, h1;
                asm volatile("ld.shared.v2.u32 {%0,%1}, [%2];"
                             : "=r"(h0), "=r"(h1) : "r"(bptr + ni * 512u));
                mma_bf16(&acc[ni * 8],     a0, h0, h1);
                mma_bf16(&acc[ni * 8 + 4], a1, h0, h1);
            }
        }

        // ---- transpose G to row-major Gs (stride 288 B), same warp region ----
#pragma unroll
        for (int ni = 0; ni < 8; ++ni) {
#pragma unroll
            for (int mi = 0; mi < 2; ++mi) {
                const float* c = &acc[ni * 8 + mi * 4];
                char* r0 = wb + (mi * 16 + g) * 288 + ni * 32 + t * 8;
                *(float2*)r0         = make_float2(c[0], c[1]);
                *(float2*)(r0 + 8 * 288) = make_float2(c[2], c[3]);
            }
        }
        __syncwarp();

        // ---- epilogue: out[f] = sum_k (G[k,f] + b2[f]) * x[j_k, f] ----
        const float* xb = x + (size_t)b * Nc * Dc;
        float o0 = 0.0f, o1 = 0.0f;
#pragma unroll
        for (int kb = 0; kb < 4; ++kb) {
            float2 xv[8];
#pragma unroll
            for (int u = 0; u < 8; ++u) {
                const int jk = __shfl_sync(0xFFFFFFFFu, j, kb * 8 + u);
                xv[u] = *(const float2*)(xb + (size_t)jk * Dc + f0);
            }
#pragma unroll
            for (int u = 0; u < 8; ++u) {
                const float2 g2 = *(const float2*)(wb + (kb * 8 + u) * 288 + lane * 8);
                o0 = fmaf(g2.x + b20, xv[u].x, o0);
                o1 = fmaf(g2.y + b21, xv[u].y, o1);
            }
        }
        __syncwarp();   // Gs region reused as H next iteration

        *(float2*)(out + (size_t)p * Dc + f0) = make_float2(o0, o1);
    }
}

extern "C" void kernel_launch(void* const* d_in, const int* in_sizes, int n_in,
                              void* d_out, int out_size) {
    const float* x    = (const float*)d_in[0];
    const float* pos  = (const float*)d_in[1];
    const int*   nidx = (const int*)  d_in[2];
    const float* W2   = (const float*)d_in[5];
    const float* b2   = (const float*)d_in[6];
    float* out = (float*)d_out;
    (void)in_sizes; (void)n_in; (void)out_size;

    // Loop-invariant small operands -> constant bank (D2D async, capturable)
    cudaMemcpyToSymbolAsync(W1c, d_in[3], 3 * 64 * sizeof(float), 0,
                            cudaMemcpyDeviceToDevice, 0);
    cudaMemcpyToSymbolAsync(B1c, d_in[4], 64 * sizeof(float), 0,
                            cudaMemcpyDeviceToDevice, 0);

    cudaFuncSetAttribute(pc_mma_kernel, cudaFuncAttributeMaxDynamicSharedMemorySize,
                         SMEM_BYTES);
    pc_mma_kernel<<<NCTA, NTHR, SMEM_BYTES>>>(x, pos, nidx, W2, b2, out);
}

// round 7
// speedup vs baseline: 1.3560x; 1.3560x over previous
#include <cuda_runtime.h>
#include <cuda_fp16.h>
#include <cstdint>
#include <cstddef>

namespace {

constexpr int Nc = 16384, Kc = 32, Dc = 64;
constexpr int POINTS = 4 * Nc;           // 65536
constexpr int NTHR   = 128;              // 4 warps / CTA
constexpr int NCTA   = 444;              // 3 CTAs / SM

// ---- shared memory layout (byte offsets) ----
constexpr int SM_BFRAG = 0;              // W2 fp16 hi/lo fragment table: 4*8*32*16 = 16384 B
constexpr int SM_W1    = 16384;          // 3*64 f32
constexpr int SM_B1    = 17152;          // 64 f32
constexpr int SM_WARP  = 17408;          // 4 per-warp regions
constexpr int PW       = 9472;           // per-warp: H fp16 [32x128B] / Gs [32x288B] overlay
constexpr int SMEM_BYTES = SM_WARP + 4 * PW;   // 55296

__device__ __forceinline__ uint32_t smem_u32(const void* p) {
    uint32_t a;
    asm("{ .reg .u64 t; cvta.to.shared.u64 t, %1; cvt.u32.u64 %0, t; }" : "=r"(a) : "l"(p));
    return a;
}
__device__ __forceinline__ uint32_t pack_h2(__half lo, __half hi) {
    return (uint32_t)__half_as_ushort(lo) | ((uint32_t)__half_as_ushort(hi) << 16);
}
__device__ __forceinline__ unsigned long long pack_f2(float lo, float hi) {
    unsigned long long d;
    asm("mov.b64 %0, {%1, %2};" : "=l"(d) : "f"(lo), "f"(hi));
    return d;
}
__device__ __forceinline__ unsigned long long ffma2(unsigned long long a,
                                                    unsigned long long b,
                                                    unsigned long long c) {
    unsigned long long d;
    asm("fma.rn.f32x2 %0, %1, %2, %3;" : "=l"(d) : "l"(a), "l"(b), "l"(c));
    return d;
}
__device__ __forceinline__ unsigned long long fmul2(unsigned long long a,
                                                    unsigned long long b) {
    unsigned long long d;
    asm("mul.rn.f32x2 %0, %1, %2;" : "=l"(d) : "l"(a), "l"(b));
    return d;
}
// fp16x2 pack from packed f32x2 pair: low half <- lo float, high <- hi float
__device__ __forceinline__ uint32_t cvt_f16x2(unsigned long long zpair) {
    uint32_t lo, hi, d;
    asm("mov.b64 {%0, %1}, %2;" : "=r"(lo), "=r"(hi) : "l"(zpair));
    asm("cvt.rn.f16x2.f32 %0, %1, %2;" : "=r"(d)
        : "f"(__uint_as_float(hi)), "f"(__uint_as_float(lo)));
    return d;
}
// packed abs: clear sign bits of both 32-bit halves
__device__ __forceinline__ unsigned long long abs2(unsigned long long a) {
    uint32_t lo, hi;
    asm("mov.b64 {%0, %1}, %2;" : "=r"(lo), "=r"(hi) : "l"(a));
    lo &= 0x7FFFFFFFu; hi &= 0x7FFFFFFFu;
    unsigned long long d;
    asm("mov.b64 %0, {%1, %2};" : "=l"(d) : "r"(lo), "r"(hi));
    return d;
}
__device__ __forceinline__ void mma_f16(float* c, const uint32_t* a,
                                        uint32_t b0, uint32_t b1) {
    asm volatile(
        "mma.sync.aligned.m16n8k16.row.col.f32.f16.f16.f32 "
        "{%0,%1,%2,%3}, {%4,%5,%6,%7}, {%8,%9}, {%0,%1,%2,%3};"
        : "+f"(c[0]), "+f"(c[1]), "+f"(c[2]), "+f"(c[3])
        : "r"(a[0]), "r"(a[1]), "r"(a[2]), "r"(a[3]), "r"(b0), "r"(b1));
}

} // namespace

__global__ void __launch_bounds__(NTHR, 3) pc_mma_kernel(
    const float* __restrict__ x,      // [B, N, 64]
    const float* __restrict__ pos,    // [B, N, 3]
    const int*   __restrict__ nidx,   // [B, N, 32]
    const float* __restrict__ W1,     // [3, 64]
    const float* __restrict__ b1,     // [64]
    const float* __restrict__ W2,     // [64, 64]  (g-major: W2[g*64+f])
    const float* __restrict__ b2,     // [64]
    float*       __restrict__ out)    // [B, N, 64]
{
    extern __shared__ char smem[];
    const uint32_t sb = smem_u32(smem);

    const int tid  = threadIdx.x;
    const int warp = tid >> 5;
    const int lane = tid & 31;
    const int f0   = 2 * lane;

    // ================= one-time init =================
    float* w1s = (float*)(smem + SM_W1);
    float* b1s = (float*)(smem + SM_B1);
    for (int i = tid; i < 3 * Dc; i += NTHR) w1s[i] = W1[i];
    for (int i = tid; i < Dc; i += NTHR)     b1s[i] = b1[i];

    // W2'' fp16 hi/lo fragment table, entry (s, ni, ln) = 16B {hi0, hi1, lo0, lo1}
    //   n = ni*8 + (ln>>2);  k0 = s*16 + (ln&3)*2
    //   hi0 = {f16(W2[k0][n]) low, f16(W2[k0+1][n]) high}; hi1 = rows k0+8, k0+9
    //   lo* = f16 of residuals (v - f32(f16(v)))
    for (int i = tid; i < 4 * 8 * 32; i += NTHR) {
        const int s = i >> 8, ni = (i >> 5) & 7, ln = i & 31;
        const int n  = ni * 8 + (ln >> 2);
        const int k0 = s * 16 + (ln & 3) * 2;
        float v[4] = { W2[k0 * Dc + n],       W2[(k0 + 1) * Dc + n],
                       W2[(k0 + 8) * Dc + n], W2[(k0 + 9) * Dc + n] };
        __half h[4], l[4];
#pragma unroll
        for (int q = 0; q < 4; ++q) {
            h[q] = __float2half_rn(v[q]);
            l[q] = __float2half_rn(v[q] - __half2float(h[q]));
        }
        uint4 e;
        e.x = pack_h2(h[0], h[1]);
        e.y = pack_h2(h[2], h[3]);
        e.z = pack_h2(l[0], l[1]);
        e.w = pack_h2(l[2], l[3]);
        *(uint4*)(smem + SM_BFRAG + (size_t)i * 16) = e;
    }
    __syncthreads();

    // ================= per-lane constants =================
    const float b20 = b2[f0], b21 = b2[f0 + 1];
    char* const wb = smem + SM_WARP + warp * PW;
    const uint32_t wbase = sb + SM_WARP + warp * PW;

    const int rl  = lane & 7;            // swizzle key (= target row & 7)
    const int grp = lane >> 3;
    const int a_row = rl + (grp & 1) * 8;
    const int csel  = grp >> 1;
    const uint32_t a_addr0 = wbase + (uint32_t)a_row * 128u;          // rows 0-15
    const uint32_t a_addr1 = wbase + (uint32_t)(a_row + 16) * 128u;   // rows 16-31
    const uint32_t bfrag_base = sb + SM_BFRAG + (uint32_t)lane * 16u;
    const int g = lane >> 2, t = lane & 3;

    const unsigned long long c055 = pack_f2(0.55f, 0.55f);
    const unsigned long long c045 = pack_f2(0.45f, 0.45f);

    const int pstride = NCTA * 4;

    // ---- prefetch state for point p ----
    int p = blockIdx.x * 4 + warp;
    int   jv = 0;
    float cxv = 0.f, cyv = 0.f, czv = 0.f, nxv = 0.f, nyv = 0.f, nzv = 0.f;
    if (p < POINTS) {
        const int bb = p >> 14;
        jv  = nidx[(size_t)p * Kc + lane];
        cxv = pos[(size_t)p * 3 + 0];
        cyv = pos[(size_t)p * 3 + 1];
        czv = pos[(size_t)p * 3 + 2];
        const float* npp = pos + (size_t)(bb * Nc + jv) * 3;
        nxv = npp[0]; nyv = npp[1]; nzv = npp[2];
    }

    for (; p < POINTS; p += pstride) {
        const int b = p >> 14;
        const int j = jv;
        const float rx = cxv - nxv, ry = cyv - nyv, rz = czv - nzv;

        const unsigned long long rx2 = pack_f2(rx, rx);
        const unsigned long long ry2 = pack_f2(ry, ry);
        const unsigned long long rz2 = pack_f2(rz, rz);

        // ---- H build (fp16, single plane): lane = row k, 8 chunks x 8 cols ----
        {
            const uint32_t hrow = wbase + (uint32_t)lane * 128u;
#pragma unroll
            for (int c = 0; c < 8; ++c) {
                uint32_t q[4];
#pragma unroll
                for (int h = 0; h < 2; ++h) {
                    const int g0 = c * 8 + h * 4;
                    // packed f32x2 pairs straight out of row-major W1/b1
                    const ulonglong2 wx = *(const ulonglong2*)(w1s + g0);
                    const ulonglong2 wy = *(const ulonglong2*)(w1s + Dc + g0);
                    const ulonglong2 wz = *(const ulonglong2*)(w1s + 2 * Dc + g0);
                    const ulonglong2 bb = *(const ulonglong2*)(b1s + g0);
                    unsigned long long z0 =
                        ffma2(rx2, wx.x, ffma2(ry2, wy.x, ffma2(rz2, wz.x, bb.x)));
                    unsigned long long z1 =
                        ffma2(rx2, wx.y, ffma2(ry2, wy.y, ffma2(rz2, wz.y, bb.y)));
                    // leaky(z) = 0.55 z + 0.45 |z|
                    z0 = ffma2(abs2(z0), c045, fmul2(z0, c055));
                    z1 = ffma2(abs2(z1), c045, fmul2(z1, c055));
                    q[2 * h]     = cvt_f16x2(z0);
                    q[2 * h + 1] = cvt_f16x2(z1);
                }
                const uint32_t pc = (uint32_t)(c ^ rl);
                asm volatile("st.shared.v4.b32 [%0], {%1,%2,%3,%4};" ::
                             "r"(hrow + (pc << 4)),
                             "r"(q[0]), "r"(q[1]), "r"(q[2]), "r"(q[3]));
            }
        }
        __syncwarp();

        // ---- prefetch next point's idx/pos (consumed next iteration) ----
        {
            const int pn = p + pstride;
            if (pn < POINTS) {
                const int bn = pn >> 14;
                jv  = nidx[(size_t)pn * Kc + lane];
                cxv = pos[(size_t)pn * 3 + 0];
                cyv = pos[(size_t)pn * 3 + 1];
                czv = pos[(size_t)pn * 3 + 2];
                const float* npp = pos + (size_t)(bn * Nc + jv) * 3;
                nxv = npp[0]; nyv = npp[1]; nzv = npp[2];
            }
        }

        // ---- GEMM: G[32x64] = H * (W2hi + W2lo), 4 k16 steps x 2 planes ----
        float acc[64];
#pragma unroll
        for (int i = 0; i < 64; ++i) acc[i] = 0.0f;

#pragma unroll
        for (int s = 0; s < 4; ++s) {
            const uint32_t cl = (uint32_t)s * 2u + (uint32_t)csel;
            const uint32_t coff = ((cl ^ (uint32_t)rl) << 4);
            uint32_t a0[4], a1[4];
            asm volatile("ldmatrix.sync.aligned.m8n8.x4.shared.b16 {%0,%1,%2,%3}, [%4];"
                         : "=r"(a0[0]), "=r"(a0[1]), "=r"(a0[2]), "=r"(a0[3])
                         : "r"(a_addr0 + coff));
            asm volatile("ldmatrix.sync.aligned.m8n8.x4.shared.b16 {%0,%1,%2,%3}, [%4];"
                         : "=r"(a1[0]), "=r"(a1[1]), "=r"(a1[2]), "=r"(a1[3])
                         : "r"(a_addr1 + coff));
            const uint32_t bptr = bfrag_base + (uint32_t)s * 4096u;
#pragma unroll
            for (int ni = 0; ni < 8; ++ni) {
                uint32_t h0, h1, l0, l1;
                asm volatile("ld.shared.v4.u32 {%0,%1,%2,%3}, [%4];"
                             : "=r"(h0), "=r"(h1), "=r"(l0), "=r"(l1)
                             : "r"(bptr + ni * 512u));
                mma_f16(&acc[ni * 8],     a0, h0, h1);
                mma_f16(&acc[ni * 8 + 4], a1, h0, h1);
                mma_f16(&acc[ni * 8],     a0, l0, l1);
                mma_f16(&acc[ni * 8 + 4], a1, l0, l1);
            }
        }

        // ---- transpose G to row-major Gs (stride 288 B), same warp region ----
#pragma unroll
        for (int ni = 0; ni < 8; ++ni) {
#pragma unroll
            for (int mi = 0; mi < 2; ++mi) {
                const float* c = &acc[ni * 8 + mi * 4];
                char* r0 = wb + (mi * 16 + g) * 288 + ni * 32 + t * 8;
                *(float2*)r0             = make_float2(c[0], c[1]);
                *(float2*)(r0 + 8 * 288) = make_float2(c[2], c[3]);
            }
        }
        __syncwarp();

        // ---- epilogue: out[f] = sum_k (G[k,f] + b2[f]) * x[j_k, f] ----
        const float* xb = x + (size_t)b * Nc * Dc;
        float o0 = 0.0f, o1 = 0.0f;
#pragma unroll
        for (int kb = 0; kb < 4; ++kb) {
            float2 xv[8];
#pragma unroll
            for (int u = 0; u < 8; ++u) {
                const int jk = __shfl_sync(0xFFFFFFFFu, j, kb * 8 + u);
                xv[u] = *(const float2*)(xb + (size_t)jk * Dc + f0);
            }
#pragma unroll
            for (int u = 0; u < 8; ++u) {
                const float2 g2 = *(const float2*)(wb + (kb * 8 + u) * 288 + lane * 8);
                o0 = fmaf(g2.x + b20, xv[u].x, o0);
                o1 = fmaf(g2.y + b21, xv[u].y, o1);
            }
        }
        __syncwarp();   // Gs region reused as H next iteration

        *(float2*)(out + (size_t)p * Dc + f0) = make_float2(o0, o1);
    }
}

extern "C" void kernel_launch(void* const* d_in, const int* in_sizes, int n_in,
                              void* d_out, int out_size) {
    const float* x    = (const float*)d_in[0];
    const float* pos  = (const float*)d_in[1];
    const int*   nidx = (const int*)  d_in[2];
    const float* W1   = (const float*)d_in[3];
    const float* b1   = (const float*)d_in[4];
    const float* W2   = (const float*)d_in[5];
    const float* b2   = (const float*)d_in[6];
    float* out = (float*)d_out;
    (void)in_sizes; (void)n_in; (void)out_size;

    cudaFuncSetAttribute(pc_mma_kernel, cudaFuncAttributeMaxDynamicSharedMemorySize,
                         SMEM_BYTES);
    pc_mma_kernel<<<NCTA, NTHR, SMEM_BYTES>>>(x, pos, nidx, W1, b1, W2, b2, out);
}

// round 8
// speedup vs baseline: 1.5380x; 1.1342x over previous
#include <cuda_runtime.h>
#include <cuda_fp16.h>
#include <cstdint>
#include <cstddef>

namespace {

constexpr int Nc = 16384, Kc = 32, Dc = 64;
constexpr int POINTS = 4 * Nc;           // 65536
constexpr int NTHR   = 128;              // 4 warps / CTA
constexpr int NCTA   = 444;              // 3 CTAs / SM

// ---- shared memory layout (byte offsets) ----
constexpr int SM_BFRAG = 0;              // W2 fp16 fragment table: 4*8*32*8 = 8192 B
constexpr int SM_W1    = 8192;           // 3*64 f32
constexpr int SM_B1    = 8960;           // 64 f32
constexpr int SM_WARP  = 9216;           // 4 per-warp regions
constexpr int PW       = 9472;           // per-warp: H fp16 [32x128B] / Gs [32x288B] overlay
constexpr int SMEM_BYTES = SM_WARP + 4 * PW;   // 47104

__device__ __forceinline__ uint32_t smem_u32(const void* p) {
    uint32_t a;
    asm("{ .reg .u64 t; cvta.to.shared.u64 t, %1; cvt.u32.u64 %0, t; }" : "=r"(a) : "l"(p));
    return a;
}
__device__ __forceinline__ uint32_t pack_h2(__half lo, __half hi) {
    return (uint32_t)__half_as_ushort(lo) | ((uint32_t)__half_as_ushort(hi) << 16);
}
__device__ __forceinline__ unsigned long long pack_f2(float lo, float hi) {
    unsigned long long d;
    asm("mov.b64 %0, {%1, %2};" : "=l"(d) : "f"(lo), "f"(hi));
    return d;
}
__device__ __forceinline__ unsigned long long ffma2(unsigned long long a,
                                                    unsigned long long b,
                                                    unsigned long long c) {
    unsigned long long d;
    asm("fma.rn.f32x2 %0, %1, %2, %3;" : "=l"(d) : "l"(a), "l"(b), "l"(c));
    return d;
}
__device__ __forceinline__ unsigned long long fmul2(unsigned long long a,
                                                    unsigned long long b) {
    unsigned long long d;
    asm("mul.rn.f32x2 %0, %1, %2;" : "=l"(d) : "l"(a), "l"(b));
    return d;
}
// fp16x2 pack from packed f32x2 pair: low half <- lo float, high <- hi float
__device__ __forceinline__ uint32_t cvt_f16x2(unsigned long long zpair) {
    uint32_t lo, hi, d;
    asm("mov.b64 {%0, %1}, %2;" : "=r"(lo), "=r"(hi) : "l"(zpair));
    asm("cvt.rn.f16x2.f32 %0, %1, %2;" : "=r"(d)
        : "f"(__uint_as_float(hi)), "f"(__uint_as_float(lo)));
    return d;
}
// packed abs: clear sign bits of both 32-bit halves
__device__ __forceinline__ unsigned long long abs2(unsigned long long a) {
    uint32_t lo, hi;
    asm("mov.b64 {%0, %1}, %2;" : "=r"(lo), "=r"(hi) : "l"(a));
    lo &= 0x7FFFFFFFu; hi &= 0x7FFFFFFFu;
    unsigned long long d;
    asm("mov.b64 %0, {%1, %2};" : "=l"(d) : "r"(lo), "r"(hi));
    return d;
}
__device__ __forceinline__ void mma_f16(float* c, const uint32_t* a,
                                        uint32_t b0, uint32_t b1) {
    asm volatile(
        "mma.sync.aligned.m16n8k16.row.col.f32.f16.f16.f32 "
        "{%0,%1,%2,%3}, {%4,%5,%6,%7}, {%8,%9}, {%0,%1,%2,%3};"
        : "+f"(c[0]), "+f"(c[1]), "+f"(c[2]), "+f"(c[3])
        : "r"(a[0]), "r"(a[1]), "r"(a[2]), "r"(a[3]), "r"(b0), "r"(b1));
}

} // namespace

__global__ void __launch_bounds__(NTHR, 3) pc_mma_kernel(
    const float* __restrict__ x,      // [B, N, 64]
    const float* __restrict__ pos,    // [B, N, 3]
    const int*   __restrict__ nidx,   // [B, N, 32]
    const float* __restrict__ W1,     // [3, 64]
    const float* __restrict__ b1,     // [64]
    const float* __restrict__ W2,     // [64, 64]  (g-major: W2[g*64+f])
    const float* __restrict__ b2,     // [64]
    float*       __restrict__ out)    // [B, N, 64]
{
    extern __shared__ char smem[];
    const uint32_t sb = smem_u32(smem);

    const int tid  = threadIdx.x;
    const int warp = tid >> 5;
    const int lane = tid & 31;
    const int f0   = 2 * lane;

    // ================= one-time init =================
    float* w1s = (float*)(smem + SM_W1);
    float* b1s = (float*)(smem + SM_B1);
    for (int i = tid; i < 3 * Dc; i += NTHR) w1s[i] = W1[i];
    for (int i = tid; i < Dc; i += NTHR)     b1s[i] = b1[i];

    // W2'' fp16 fragment table (single plane), entry (s, ni, ln) = 8B {b0, b1}
    //   n = ni*8 + (ln>>2);  k0 = s*16 + (ln&3)*2
    //   b0 = {f16(W2[k0][n]), f16(W2[k0+1][n])}; b1 = rows k0+8, k0+9
    for (int i = tid; i < 4 * 8 * 32; i += NTHR) {
        const int s = i >> 8, ni = (i >> 5) & 7, ln = i & 31;
        const int n  = ni * 8 + (ln >> 2);
        const int k0 = s * 16 + (ln & 3) * 2;
        uint2 e;
        e.x = pack_h2(__float2half_rn(W2[k0 * Dc + n]),
                      __float2half_rn(W2[(k0 + 1) * Dc + n]));
        e.y = pack_h2(__float2half_rn(W2[(k0 + 8) * Dc + n]),
                      __float2half_rn(W2[(k0 + 9) * Dc + n]));
        *(uint2*)(smem + SM_BFRAG + (size_t)i * 8) = e;
    }
    __syncthreads();

    // ================= per-lane constants =================
    const float b20 = b2[f0], b21 = b2[f0 + 1];
    char* const wb = smem + SM_WARP + warp * PW;
    const uint32_t wbase = sb + SM_WARP + warp * PW;

    const int rl  = lane & 7;            // swizzle key (= target row & 7)
    const int grp = lane >> 3;
    const int a_row = rl + (grp & 1) * 8;
    const int csel  = grp >> 1;
    const uint32_t a_addr0 = wbase + (uint32_t)a_row * 128u;          // rows 0-15
    const uint32_t a_addr1 = wbase + (uint32_t)(a_row + 16) * 128u;   // rows 16-31
    const uint32_t bfrag_base = sb + SM_BFRAG + (uint32_t)lane * 8u;
    const int g = lane >> 2, t = lane & 3;

    const unsigned long long c055 = pack_f2(0.55f, 0.55f);
    const unsigned long long c045 = pack_f2(0.45f, 0.45f);

    const int pstride = NCTA * 4;

    // ---- prefetch state for point p ----
    int p = blockIdx.x * 4 + warp;
    int   jv = 0;
    float cxv = 0.f, cyv = 0.f, czv = 0.f, nxv = 0.f, nyv = 0.f, nzv = 0.f;
    if (p < POINTS) {
        const int bb = p >> 14;
        jv  = nidx[(size_t)p * Kc + lane];
        cxv = pos[(size_t)p * 3 + 0];
        cyv = pos[(size_t)p * 3 + 1];
        czv = pos[(size_t)p * 3 + 2];
        const float* npp = pos + (size_t)(bb * Nc + jv) * 3;
        nxv = npp[0]; nyv = npp[1]; nzv = npp[2];
    }

    for (; p < POINTS; p += pstride) {
        const int b = p >> 14;
        const int j = jv;
        const float rx = cxv - nxv, ry = cyv - nyv, rz = czv - nzv;

        const unsigned long long rx2 = pack_f2(rx, rx);
        const unsigned long long ry2 = pack_f2(ry, ry);
        const unsigned long long rz2 = pack_f2(rz, rz);

        // ---- H build (fp16, single plane): lane = row k, 8 chunks x 8 cols ----
        {
            const uint32_t hrow = wbase + (uint32_t)lane * 128u;
#pragma unroll
            for (int c = 0; c < 8; ++c) {
                uint32_t q[4];
#pragma unroll
                for (int h = 0; h < 2; ++h) {
                    const int g0 = c * 8 + h * 4;
                    // packed f32x2 pairs straight out of row-major W1/b1
                    const ulonglong2 wx = *(const ulonglong2*)(w1s + g0);
                    const ulonglong2 wy = *(const ulonglong2*)(w1s + Dc + g0);
                    const ulonglong2 wz = *(const ulonglong2*)(w1s + 2 * Dc + g0);
                    const ulonglong2 bb = *(const ulonglong2*)(b1s + g0);
                    unsigned long long z0 =
                        ffma2(rx2, wx.x, ffma2(ry2, wy.x, ffma2(rz2, wz.x, bb.x)));
                    unsigned long long z1 =
                        ffma2(rx2, wx.y, ffma2(ry2, wy.y, ffma2(rz2, wz.y, bb.y)));
                    // leaky(z) = 0.55 z + 0.45 |z|
                    z0 = ffma2(abs2(z0), c045, fmul2(z0, c055));
                    z1 = ffma2(abs2(z1), c045, fmul2(z1, c055));
                    q[2 * h]     = cvt_f16x2(z0);
                    q[2 * h + 1] = cvt_f16x2(z1);
                }
                const uint32_t pc = (uint32_t)(c ^ rl);
                asm volatile("st.shared.v4.b32 [%0], {%1,%2,%3,%4};" ::
                             "r"(hrow + (pc << 4)),
                             "r"(q[0]), "r"(q[1]), "r"(q[2]), "r"(q[3]));
            }
        }
        __syncwarp();

        // ---- prefetch next point's idx/pos (consumed next iteration) ----
        {
            const int pn = p + pstride;
            if (pn < POINTS) {
                const int bn = pn >> 14;
                jv  = nidx[(size_t)pn * Kc + lane];
                cxv = pos[(size_t)pn * 3 + 0];
                cyv = pos[(size_t)pn * 3 + 1];
                czv = pos[(size_t)pn * 3 + 2];
                const float* npp = pos + (size_t)(bn * Nc + jv) * 3;
                nxv = npp[0]; nyv = npp[1]; nzv = npp[2];
            }
        }

        // ---- GEMM: G[32x64] = H * W2 (fp16 single plane), 4 k16 steps ----
        float acc[64];
#pragma unroll
        for (int i = 0; i < 64; ++i) acc[i] = 0.0f;

#pragma unroll
        for (int s = 0; s < 4; ++s) {
            const uint32_t cl = (uint32_t)s * 2u + (uint32_t)csel;
            const uint32_t coff = ((cl ^ (uint32_t)rl) << 4);
            uint32_t a0[4], a1[4];
            asm volatile("ldmatrix.sync.aligned.m8n8.x4.shared.b16 {%0,%1,%2,%3}, [%4];"
                         : "=r"(a0[0]), "=r"(a0[1]), "=r"(a0[2]), "=r"(a0[3])
                         : "r"(a_addr0 + coff));
            asm volatile("ldmatrix.sync.aligned.m8n8.x4.shared.b16 {%0,%1,%2,%3}, [%4];"
                         : "=r"(a1[0]), "=r"(a1[1]), "=r"(a1[2]), "=r"(a1[3])
                         : "r"(a_addr1 + coff));
            const uint32_t bptr = bfrag_base + (uint32_t)s * 2048u;
#pragma unroll
            for (int ni = 0; ni < 8; ++ni) {
                uint32_t h0, h1;
                asm volatile("ld.shared.v2.u32 {%0,%1}, [%2];"
                             : "=r"(h0), "=r"(h1) : "r"(bptr + ni * 256u));
                mma_f16(&acc[ni * 8],     a0, h0, h1);
                mma_f16(&acc[ni * 8 + 4], a1, h0, h1);
            }
        }

        // ---- transpose G to row-major Gs (stride 288 B), same warp region ----
#pragma unroll
        for (int ni = 0; ni < 8; ++ni) {
#pragma unroll
            for (int mi = 0; mi < 2; ++mi) {
                const float* c = &acc[ni * 8 + mi * 4];
                char* r0 = wb + (mi * 16 + g) * 288 + ni * 32 + t * 8;
                *(float2*)r0             = make_float2(c[0], c[1]);
                *(float2*)(r0 + 8 * 288) = make_float2(c[2], c[3]);
            }
        }
        __syncwarp();

        // ---- epilogue: out[f] = sum_k (G[k,f] + b2[f]) * x[j_k, f] ----
        const float* xb = x + (size_t)b * Nc * Dc;
        float o0 = 0.0f, o1 = 0.0f;
#pragma unroll
        for (int kb = 0; kb < 4; ++kb) {
            float2 xv[8];
#pragma unroll
            for (int u = 0; u < 8; ++u) {
                const int jk = __shfl_sync(0xFFFFFFFFu, j, kb * 8 + u);
                xv[u] = *(const float2*)(xb + (size_t)jk * Dc + f0);
            }
#pragma unroll
            for (int u = 0; u < 8; ++u) {
                const float2 g2 = *(const float2*)(wb + (kb * 8 + u) * 288 + lane * 8);
                o0 = fmaf(g2.x + b20, xv[u].x, o0);
                o1 = fmaf(g2.y + b21, xv[u].y, o1);
            }
        }
        __syncwarp();   // Gs region reused as H next iteration

        *(float2*)(out + (size_t)p * Dc + f0) = make_float2(o0, o1);
    }
}

extern "C" void kernel_launch(void* const* d_in, const int* in_sizes, int n_in,
                              void* d_out, int out_size) {
    const float* x    = (const float*)d_in[0];
    const float* pos  = (const float*)d_in[1];
    const int*   nidx = (const int*)  d_in[2];
    const float* W1   = (const float*)d_in[3];
    const float* b1   = (const float*)d_in[4];
    const float* W2   = (const float*)d_in[5];
    const float* b2   = (const float*)d_in[6];
    float* out = (float*)d_out;
    (void)in_sizes; (void)n_in; (void)out_size;

    cudaFuncSetAttribute(pc_mma_kernel, cudaFuncAttributeMaxDynamicSharedMemorySize,
                         SMEM_BYTES);
    pc_mma_kernel<<<NCTA, NTHR, SMEM_BYTES>>>(x, pos, nidx, W1, b1, W2, b2, out);
}

// round 9
// speedup vs baseline: 1.6949x; 1.1020x over previous
#include <cuda_runtime.h>
#include <cuda_fp16.h>
#include <cstdint>
#include <cstddef>

namespace {

constexpr int Nc = 16384, Kc = 32, Dc = 64;
constexpr int POINTS = 4 * Nc;           // 65536
constexpr int NTHR   = 128;              // 4 warps / CTA
constexpr int NCTA   = 444;              // 3 CTAs / SM

// ---- shared memory layout (byte offsets) ----
constexpr int SM_BFRAG = 0;              // W2 fp16 fragment table: 4*8*32*8 = 8192 B
constexpr int SM_W1    = 8192;           // 3*64 f32
constexpr int SM_B1    = 8960;           // 64 f32
constexpr int SM_WARP  = 9216;           // 4 per-warp regions
constexpr int PW       = 4736;           // per-warp: H fp16 [32x128B] / Gs16 [32x144B] overlay
constexpr int SMEM_BYTES = SM_WARP + 4 * PW;   // 28160
constexpr int GSTRIDE = 144;             // Gs16 row stride in bytes (36 u32)

__device__ __forceinline__ uint32_t smem_u32(const void* p) {
    uint32_t a;
    asm("{ .reg .u64 t; cvta.to.shared.u64 t, %1; cvt.u32.u64 %0, t; }" : "=r"(a) : "l"(p));
    return a;
}
__device__ __forceinline__ uint32_t pack_h2(__half lo, __half hi) {
    return (uint32_t)__half_as_ushort(lo) | ((uint32_t)__half_as_ushort(hi) << 16);
}
__device__ __forceinline__ unsigned long long pack_f2(float lo, float hi) {
    unsigned long long d;
    asm("mov.b64 %0, {%1, %2};" : "=l"(d) : "f"(lo), "f"(hi));
    return d;
}
__device__ __forceinline__ unsigned long long ffma2(unsigned long long a,
                                                    unsigned long long b,
                                                    unsigned long long c) {
    unsigned long long d;
    asm("fma.rn.f32x2 %0, %1, %2, %3;" : "=l"(d) : "l"(a), "l"(b), "l"(c));
    return d;
}
__device__ __forceinline__ unsigned long long fmul2(unsigned long long a,
                                                    unsigned long long b) {
    unsigned long long d;
    asm("mul.rn.f32x2 %0, %1, %2;" : "=l"(d) : "l"(a), "l"(b));
    return d;
}
// fp16x2 pack from packed f32x2 pair
__device__ __forceinline__ uint32_t cvt_f16x2(unsigned long long zpair) {
    uint32_t lo, hi, d;
    asm("mov.b64 {%0, %1}, %2;" : "=r"(lo), "=r"(hi) : "l"(zpair));
    asm("cvt.rn.f16x2.f32 %0, %1, %2;" : "=r"(d)
        : "f"(__uint_as_float(hi)), "f"(__uint_as_float(lo)));
    return d;
}
// fp16x2 pack from two floats: low half <- a, high half <- b
__device__ __forceinline__ uint32_t cvt_f16x2_ff(float a, float b) {
    uint32_t d;
    asm("cvt.rn.f16x2.f32 %0, %1, %2;" : "=r"(d) : "f"(b), "f"(a));
    return d;
}
// unpack fp16x2 -> two f32
__device__ __forceinline__ void unpack_h2(uint32_t v, float& a, float& b) {
    asm("{ .reg .b16 l, h;\n\t"
        "mov.b32 {l, h}, %2;\n\t"
        "cvt.f32.f16 %0, l;\n\t"
        "cvt.f32.f16 %1, h; }"
        : "=f"(a), "=f"(b) : "r"(v));
}
// packed abs: clear sign bits of both 32-bit halves
__device__ __forceinline__ unsigned long long abs2(unsigned long long a) {
    uint32_t lo, hi;
    asm("mov.b64 {%0, %1}, %2;" : "=r"(lo), "=r"(hi) : "l"(a));
    lo &= 0x7FFFFFFFu; hi &= 0x7FFFFFFFu;
    unsigned long long d;
    asm("mov.b64 %0, {%1, %2};" : "=l"(d) : "r"(lo), "r"(hi));
    return d;
}
__device__ __forceinline__ void mma_f16(float* c, const uint32_t* a,
                                        uint32_t b0, uint32_t b1) {
    asm volatile(
        "mma.sync.aligned.m16n8k16.row.col.f32.f16.f16.f32 "
        "{%0,%1,%2,%3}, {%4,%5,%6,%7}, {%8,%9}, {%0,%1,%2,%3};"
        : "+f"(c[0]), "+f"(c[1]), "+f"(c[2]), "+f"(c[3])
        : "r"(a[0]), "r"(a[1]), "r"(a[2]), "r"(a[3]), "r"(b0), "r"(b1));
}

} // namespace

__global__ void __launch_bounds__(NTHR, 3) pc_mma_kernel(
    const float* __restrict__ x,      // [B, N, 64]
    const float* __restrict__ pos,    // [B, N, 3]
    const int*   __restrict__ nidx,   // [B, N, 32]
    const float* __restrict__ W1,     // [3, 64]
    const float* __restrict__ b1,     // [64]
    const float* __restrict__ W2,     // [64, 64]  (g-major: W2[g*64+f])
    const float* __restrict__ b2,     // [64]
    float*       __restrict__ out)    // [B, N, 64]
{
    extern __shared__ char smem[];
    const uint32_t sb = smem_u32(smem);

    const int tid  = threadIdx.x;
    const int warp = tid >> 5;
    const int lane = tid & 31;
    const int f0   = 2 * lane;

    // ================= one-time init =================
    float* w1s = (float*)(smem + SM_W1);
    float* b1s = (float*)(smem + SM_B1);
    for (int i = tid; i < 3 * Dc; i += NTHR) w1s[i] = W1[i];
    for (int i = tid; i < Dc; i += NTHR)     b1s[i] = b1[i];

    // W2'' fp16 fragment table (single plane), entry (s, ni, ln) = 8B {b0, b1}
    for (int i = tid; i < 4 * 8 * 32; i += NTHR) {
        const int s = i >> 8, ni = (i >> 5) & 7, ln = i & 31;
        const int n  = ni * 8 + (ln >> 2);
        const int k0 = s * 16 + (ln & 3) * 2;
        uint2 e;
        e.x = pack_h2(__float2half_rn(W2[k0 * Dc + n]),
                      __float2half_rn(W2[(k0 + 1) * Dc + n]));
        e.y = pack_h2(__float2half_rn(W2[(k0 + 8) * Dc + n]),
                      __float2half_rn(W2[(k0 + 9) * Dc + n]));
        *(uint2*)(smem + SM_BFRAG + (size_t)i * 8) = e;
    }
    __syncthreads();

    // ================= per-lane constants =================
    const float b20 = b2[f0], b21 = b2[f0 + 1];
    char* const wb = smem + SM_WARP + warp * PW;
    const uint32_t wbase = sb + SM_WARP + warp * PW;

    const int rl  = lane & 7;            // swizzle key (= target row & 7)
    const int grp = lane >> 3;
    const int a_row = rl + (grp & 1) * 8;
    const int csel  = grp >> 1;
    const uint32_t a_addr0 = wbase + (uint32_t)a_row * 128u;          // rows 0-15
    const uint32_t a_addr1 = wbase + (uint32_t)(a_row + 16) * 128u;   // rows 16-31
    const uint32_t bfrag_base = sb + SM_BFRAG + (uint32_t)lane * 8u;
    const int g = lane >> 2, t = lane & 3;

    const unsigned long long c055 = pack_f2(0.55f, 0.55f);
    const unsigned long long c045 = pack_f2(0.45f, 0.45f);

    const int pstride = NCTA * 4;

    // ---- prefetch state for point p ----
    int p = blockIdx.x * 4 + warp;
    int   jv = 0;
    float cxv = 0.f, cyv = 0.f, czv = 0.f, nxv = 0.f, nyv = 0.f, nzv = 0.f;
    if (p < POINTS) {
        const int bb = p >> 14;
        jv  = nidx[(size_t)p * Kc + lane];
        cxv = pos[(size_t)p * 3 + 0];
        cyv = pos[(size_t)p * 3 + 1];
        czv = pos[(size_t)p * 3 + 2];
        const float* npp = pos + (size_t)(bb * Nc + jv) * 3;
        nxv = npp[0]; nyv = npp[1]; nzv = npp[2];
    }

    for (; p < POINTS; p += pstride) {
        const int b = p >> 14;
        const int j = jv;
        const float rx = cxv - nxv, ry = cyv - nyv, rz = czv - nzv;

        const unsigned long long rx2 = pack_f2(rx, rx);
        const unsigned long long ry2 = pack_f2(ry, ry);
        const unsigned long long rz2 = pack_f2(rz, rz);

        // ---- H build (fp16, single plane): lane = row k, 8 chunks x 8 cols ----
        {
            const uint32_t hrow = wbase + (uint32_t)lane * 128u;
#pragma unroll
            for (int c = 0; c < 8; ++c) {
                uint32_t q[4];
#pragma unroll
                for (int h = 0; h < 2; ++h) {
                    const int g0 = c * 8 + h * 4;
                    const ulonglong2 wx = *(const ulonglong2*)(w1s + g0);
                    const ulonglong2 wy = *(const ulonglong2*)(w1s + Dc + g0);
                    const ulonglong2 wz = *(const ulonglong2*)(w1s + 2 * Dc + g0);
                    const ulonglong2 bb = *(const ulonglong2*)(b1s + g0);
                    unsigned long long z0 =
                        ffma2(rx2, wx.x, ffma2(ry2, wy.x, ffma2(rz2, wz.x, bb.x)));
                    unsigned long long z1 =
                        ffma2(rx2, wx.y, ffma2(ry2, wy.y, ffma2(rz2, wz.y, bb.y)));
                    // leaky(z) = 0.55 z + 0.45 |z|
                    z0 = ffma2(abs2(z0), c045, fmul2(z0, c055));
                    z1 = ffma2(abs2(z1), c045, fmul2(z1, c055));
                    q[2 * h]     = cvt_f16x2(z0);
                    q[2 * h + 1] = cvt_f16x2(z1);
                }
                const uint32_t pc = (uint32_t)(c ^ rl);
                asm volatile("st.shared.v4.b32 [%0], {%1,%2,%3,%4};" ::
                             "r"(hrow + (pc << 4)),
                             "r"(q[0]), "r"(q[1]), "r"(q[2]), "r"(q[3]));
            }
        }
        __syncwarp();

        // ---- prefetch next point's idx/pos (consumed next iteration) ----
        {
            const int pn = p + pstride;
            if (pn < POINTS) {
                const int bn = pn >> 14;
                jv  = nidx[(size_t)pn * Kc + lane];
                cxv = pos[(size_t)pn * 3 + 0];
                cyv = pos[(size_t)pn * 3 + 1];
                czv = pos[(size_t)pn * 3 + 2];
                const float* npp = pos + (size_t)(bn * Nc + jv) * 3;
                nxv = npp[0]; nyv = npp[1]; nzv = npp[2];
            }
        }

        // ---- GEMM: G[32x64] = H * W2 (fp16 single plane), 4 k16 steps ----
        float acc[64];
#pragma unroll
        for (int i = 0; i < 64; ++i) acc[i] = 0.0f;

#pragma unroll
        for (int s = 0; s < 4; ++s) {
            const uint32_t cl = (uint32_t)s * 2u + (uint32_t)csel;
            const uint32_t coff = ((cl ^ (uint32_t)rl) << 4);
            uint32_t a0[4], a1[4];
            asm volatile("ldmatrix.sync.aligned.m8n8.x4.shared.b16 {%0,%1,%2,%3}, [%4];"
                         : "=r"(a0[0]), "=r"(a0[1]), "=r"(a0[2]), "=r"(a0[3])
                         : "r"(a_addr0 + coff));
            asm volatile("ldmatrix.sync.aligned.m8n8.x4.shared.b16 {%0,%1,%2,%3}, [%4];"
                         : "=r"(a1[0]), "=r"(a1[1]), "=r"(a1[2]), "=r"(a1[3])
                         : "r"(a_addr1 + coff));
            const uint32_t bptr = bfrag_base + (uint32_t)s * 2048u;
#pragma unroll
            for (int ni = 0; ni < 8; ++ni) {
                uint32_t h0, h1;
                asm volatile("ld.shared.v2.u32 {%0,%1}, [%2];"
                             : "=r"(h0), "=r"(h1) : "r"(bptr + ni * 256u));
                mma_f16(&acc[ni * 8],     a0, h0, h1);
                mma_f16(&acc[ni * 8 + 4], a1, h0, h1);
            }
        }

        // ---- transpose G to fp16x2 Gs16 [32 rows x 144B], same warp region ----
        // value (row m, colpair (2t..2t+1 of ni)) -> u32 at [m][ni*4 + t]
        {
            const uint32_t gdst = wbase + (uint32_t)((lane & 3) * 4 + (lane >> 2) * GSTRIDE);
#pragma unroll
            for (int ni = 0; ni < 8; ++ni) {
#pragma unroll
                for (int mi = 0; mi < 2; ++mi) {
                    const float* c = &acc[ni * 8 + mi * 4];
                    const uint32_t u0 = cvt_f16x2_ff(c[0], c[1]);
                    const uint32_t u1 = cvt_f16x2_ff(c[2], c[3]);
                    const uint32_t a = gdst + (uint32_t)(mi * 16 * GSTRIDE + ni * 16);
                    asm volatile("st.shared.b32 [%0], %1;" :: "r"(a), "r"(u0));
                    asm volatile("st.shared.b32 [%0], %1;" :: "r"(a + 8 * GSTRIDE), "r"(u1));
                }
            }
        }
        __syncwarp();

        // ---- epilogue: out[f] = sum_k (G[k,f] + b2[f]) * x[j_k, f] ----
        const float* xb = x + (size_t)b * Nc * Dc;
        const uint32_t gsrc = wbase + (uint32_t)lane * 4u;
        float o0 = 0.0f, o1 = 0.0f;
#pragma unroll
        for (int kb = 0; kb < 4; ++kb) {
            float2 xv[8];
#pragma unroll
            for (int u = 0; u < 8; ++u) {
                const int jk = __shfl_sync(0xFFFFFFFFu, j, kb * 8 + u);
                xv[u] = *(const float2*)(xb + (size_t)jk * Dc + f0);
            }
#pragma unroll
            for (int u = 0; u < 8; ++u) {
                uint32_t gv;
                asm volatile("ld.shared.b32 %0, [%1];"
                             : "=r"(gv) : "r"(gsrc + (uint32_t)((kb * 8 + u) * GSTRIDE)));
                float g0, g1;
                unpack_h2(gv, g0, g1);
                o0 = fmaf(g0 + b20, xv[u].x, o0);
                o1 = fmaf(g1 + b21, xv[u].y, o1);
            }
        }
        __syncwarp();   // Gs region reused as H next iteration

        *(float2*)(out + (size_t)p * Dc + f0) = make_float2(o0, o1);
    }
}

extern "C" void kernel_launch(void* const* d_in, const int* in_sizes, int n_in,
                              void* d_out, int out_size) {
    const float* x    = (const float*)d_in[0];
    const float* pos  = (const float*)d_in[1];
    const int*   nidx = (const int*)  d_in[2];
    const float* W1   = (const float*)d_in[3];
    const float* b1   = (const float*)d_in[4];
    const float* W2   = (const float*)d_in[5];
    const float* b2   = (const float*)d_in[6];
    float* out = (float*)d_out;
    (void)in_sizes; (void)n_in; (void)out_size;

    cudaFuncSetAttribute(pc_mma_kernel, cudaFuncAttributeMaxDynamicSharedMemorySize,
                         SMEM_BYTES);
    pc_mma_kernel<<<NCTA, NTHR, SMEM_BYTES>>>(x, pos, nidx, W1, b1, W2, b2, out);
}

// round 10
// speedup vs baseline: 1.8473x; 1.0899x over previous
#include <cuda_runtime.h>
#include <cuda_fp16.h>
#include <cstdint>
#include <cstddef>

namespace {

constexpr int Nc = 16384, Kc = 32, Dc = 64;
constexpr int POINTS = 4 * Nc;           // 65536
constexpr int NTHR   = 128;              // 4 warps / CTA
constexpr int NCTA   = 444;              // 3 CTAs / SM

// ---- shared memory layout (byte offsets) ----
constexpr int SM_BFRAG = 0;              // W2 fp16 fragment table: 4*8*32*8 = 8192 B
constexpr int SM_W1Q   = 8192;           // packed W1/b1 col-pair table: 32*32 = 1024 B
constexpr int SM_WARP  = 9216;           // 4 per-warp Gs16 regions
constexpr int PW       = 4608;           // Gs16 [32 x 144B]
constexpr int SMEM_BYTES = SM_WARP + 4 * PW;   // 27648
constexpr int GSTRIDE = 144;

__device__ __forceinline__ uint32_t smem_u32(const void* p) {
    uint32_t a;
    asm("{ .reg .u64 t; cvta.to.shared.u64 t, %1; cvt.u32.u64 %0, t; }" : "=r"(a) : "l"(p));
    return a;
}
__device__ __forceinline__ uint32_t pack_h2(__half lo, __half hi) {
    return (uint32_t)__half_as_ushort(lo) | ((uint32_t)__half_as_ushort(hi) << 16);
}
__device__ __forceinline__ unsigned long long pack_f2(float lo, float hi) {
    unsigned long long d;
    asm("mov.b64 %0, {%1, %2};" : "=l"(d) : "f"(lo), "f"(hi));
    return d;
}
__device__ __forceinline__ unsigned long long ffma2(unsigned long long a,
                                                    unsigned long long b,
                                                    unsigned long long c) {
    unsigned long long d;
    asm("fma.rn.f32x2 %0, %1, %2, %3;" : "=l"(d) : "l"(a), "l"(b), "l"(c));
    return d;
}
__device__ __forceinline__ unsigned long long fmul2(unsigned long long a,
                                                    unsigned long long b) {
    unsigned long long d;
    asm("mul.rn.f32x2 %0, %1, %2;" : "=l"(d) : "l"(a), "l"(b));
    return d;
}
__device__ __forceinline__ uint32_t cvt_f16x2(unsigned long long zpair) {
    uint32_t lo, hi, d;
    asm("mov.b64 {%0, %1}, %2;" : "=r"(lo), "=r"(hi) : "l"(zpair));
    asm("cvt.rn.f16x2.f32 %0, %1, %2;" : "=r"(d)
        : "f"(__uint_as_float(hi)), "f"(__uint_as_float(lo)));
    return d;
}
__device__ __forceinline__ uint32_t cvt_f16x2_ff(float a, float b) {
    uint32_t d;
    asm("cvt.rn.f16x2.f32 %0, %1, %2;" : "=r"(d) : "f"(b), "f"(a));
    return d;
}
__device__ __forceinline__ void unpack_h2(uint32_t v, float& a, float& b) {
    asm("{ .reg .b16 l, h;\n\t"
        "mov.b32 {l, h}, %2;\n\t"
        "cvt.f32.f16 %0, l;\n\t"
        "cvt.f32.f16 %1, h; }"
        : "=f"(a), "=f"(b) : "r"(v));
}
__device__ __forceinline__ unsigned long long abs2(unsigned long long a) {
    uint32_t lo, hi;
    asm("mov.b64 {%0, %1}, %2;" : "=r"(lo), "=r"(hi) : "l"(a));
    lo &= 0x7FFFFFFFu; hi &= 0x7FFFFFFFu;
    unsigned long long d;
    asm("mov.b64 %0, {%1, %2};" : "=l"(d) : "r"(lo), "r"(hi));
    return d;
}
__device__ __forceinline__ void mma_f16(float* c, const uint32_t* a,
                                        uint32_t b0, uint32_t b1) {
    asm volatile(
        "mma.sync.aligned.m16n8k16.row.col.f32.f16.f16.f32 "
        "{%0,%1,%2,%3}, {%4,%5,%6,%7}, {%8,%9}, {%0,%1,%2,%3};"
        : "+f"(c[0]), "+f"(c[1]), "+f"(c[2]), "+f"(c[3])
        : "r"(a[0]), "r"(a[1]), "r"(a[2]), "r"(a[3]), "r"(b0), "r"(b1));
}
// one fragment reg: fp16x2 of leaky(rel . W1[:,c0..c0+1] + b1) for one row
__device__ __forceinline__ uint32_t frag_pair(
    unsigned long long rpx, unsigned long long rpy, unsigned long long rpz,
    unsigned long long wx, unsigned long long wy, unsigned long long wz,
    unsigned long long bb,
    unsigned long long c055, unsigned long long c045) {
    unsigned long long z = ffma2(rpx, wx, ffma2(rpy, wy, ffma2(rpz, wz, bb)));
    z = ffma2(abs2(z), c045, fmul2(z, c055));   // leaky = 0.55 z + 0.45 |z|
    return cvt_f16x2(z);
}

} // namespace

// x pre-converted to fp16 (8 MB static scratch; written by cvt_x_kernel)
__device__ __half2 g_xh[(size_t)4 * 16384 * 32];

__global__ void cvt_x_kernel(const float* __restrict__ x) {
    const int i = blockIdx.x * blockDim.x + threadIdx.x;   // 2,097,152 threads
    const float2 v = ((const float2*)x)[i];
    g_xh[i] = __floats2half2_rn(v.x, v.y);
}

__global__ void __launch_bounds__(NTHR, 3) pc_mma_kernel(
    const float* __restrict__ pos,    // [B, N, 3]
    const int*   __restrict__ nidx,   // [B, N, 32]
    const float* __restrict__ W1,     // [3, 64]
    const float* __restrict__ b1,     // [64]
    const float* __restrict__ W2,     // [64, 64]
    const float* __restrict__ b2,     // [64]
    float*       __restrict__ out)    // [B, N, 64]
{
    extern __shared__ char smem[];
    const uint32_t sb = smem_u32(smem);

    const int tid  = threadIdx.x;
    const int warp = tid >> 5;
    const int lane = tid & 31;
    const int f0   = 2 * lane;
    const int q    = lane >> 2;       // fragment row base
    const int r    = lane & 3;        // fragment col-pair selector

    // ================= one-time init =================
    // W2'' fp16 fragment table (single plane), entry (s, ni, ln) = 8B {b0, b1}
    for (int i = tid; i < 4 * 8 * 32; i += NTHR) {
        const int s = i >> 8, ni = (i >> 5) & 7, ln = i & 31;
        const int n  = ni * 8 + (ln >> 2);
        const int k0 = s * 16 + (ln & 3) * 2;
        uint2 e;
        e.x = pack_h2(__float2half_rn(W2[k0 * Dc + n]),
                      __float2half_rn(W2[(k0 + 1) * Dc + n]));
        e.y = pack_h2(__float2half_rn(W2[(k0 + 8) * Dc + n]),
                      __float2half_rn(W2[(k0 + 9) * Dc + n]));
        *(uint2*)(smem + SM_BFRAG + (size_t)i * 8) = e;
    }
    // W1/b1 col-pair table: entry e = (s*2+d)*4 + r, 32B:
    //   {W1[0][c0],W1[0][c0+1]} {W1[1][..]} {W1[2][..]} {b1[..]},  c0=16s+2r+8d
    for (int e = tid; e < 32; e += NTHR) {
        const int er = e & 3, ed = (e >> 2) & 1, es = e >> 3;
        const int c0 = 16 * es + 2 * er + 8 * ed;
        float2* dst = (float2*)(smem + SM_W1Q + (size_t)e * 32);
        dst[0] = make_float2(W1[c0],          W1[c0 + 1]);
        dst[1] = make_float2(W1[Dc + c0],     W1[Dc + c0 + 1]);
        dst[2] = make_float2(W1[2 * Dc + c0], W1[2 * Dc + c0 + 1]);
        dst[3] = make_float2(b1[c0],          b1[c0 + 1]);
    }
    __syncthreads();

    // ================= per-lane constants =================
    const float b20 = b2[f0], b21 = b2[f0 + 1];
    const uint32_t wbase = sb + SM_WARP + warp * PW;          // Gs16 region
    const uint32_t bfrag_base = sb + SM_W1Q - SM_W1Q + SM_BFRAG + (uint32_t)lane * 8u;
    const uint32_t w1q_base = sb + SM_W1Q + (uint32_t)r * 32u;

    const unsigned long long c055 = pack_f2(0.55f, 0.55f);
    const unsigned long long c045 = pack_f2(0.45f, 0.45f);

    const int pstride = NCTA * 4;

    // ---- prefetch state for point p ----
    int p = blockIdx.x * 4 + warp;
    int   jv = 0;
    float cxv = 0.f, cyv = 0.f, czv = 0.f, nxv = 0.f, nyv = 0.f, nzv = 0.f;
    if (p < POINTS) {
        const int bb = p >> 14;
        jv  = nidx[(size_t)p * Kc + lane];
        cxv = pos[(size_t)p * 3 + 0];
        cyv = pos[(size_t)p * 3 + 1];
        czv = pos[(size_t)p * 3 + 2];
        const float* npp = pos + (size_t)(bb * Nc + jv) * 3;
        nxv = npp[0]; nyv = npp[1]; nzv = npp[2];
    }

    for (; p < POINTS; p += pstride) {
        const int b = p >> 14;
        const int j = jv;
        const float rx = cxv - nxv, ry = cyv - nyv, rz = czv - nzv;

        // ---- rel for this lane's 4 fragment rows (q, q+8, q+16, q+24) ----
        unsigned long long rpx[4], rpy[4], rpz[4];
#pragma unroll
        for (int i = 0; i < 4; ++i) {
            const int src = q + 8 * i;
            const float vx = __shfl_sync(0xFFFFFFFFu, rx, src);
            const float vy = __shfl_sync(0xFFFFFFFFu, ry, src);
            const float vz = __shfl_sync(0xFFFFFFFFu, rz, src);
            rpx[i] = pack_f2(vx, vx);
            rpy[i] = pack_f2(vy, vy);
            rpz[i] = pack_f2(vz, vz);
        }

        // ---- prefetch next point's idx/pos (consumed next iteration) ----
        {
            const int pn = p + pstride;
            if (pn < POINTS) {
                const int bn = pn >> 14;
                jv  = nidx[(size_t)pn * Kc + lane];
                cxv = pos[(size_t)pn * 3 + 0];
                cyv = pos[(size_t)pn * 3 + 1];
                czv = pos[(size_t)pn * 3 + 2];
                const float* npp = pos + (size_t)(bn * Nc + jv) * 3;
                nxv = npp[0]; nyv = npp[1]; nzv = npp[2];
            }
        }

        // ---- GEMM with A fragments built in-register, 4 k16 steps ----
        float acc[64];
#pragma unroll
        for (int i = 0; i < 64; ++i) acc[i] = 0.0f;

#pragma unroll
        for (int s = 0; s < 4; ++s) {
            unsigned long long wx0, wy0, wz0, bb0, wx1, wy1, wz1, bb1;
            const uint32_t qa = w1q_base + (uint32_t)(s * 256);
            asm("ld.shared.v2.b64 {%0,%1}, [%2];" : "=l"(wx0), "=l"(wy0) : "r"(qa));
            asm("ld.shared.v2.b64 {%0,%1}, [%2];" : "=l"(wz0), "=l"(bb0) : "r"(qa + 16));
            asm("ld.shared.v2.b64 {%0,%1}, [%2];" : "=l"(wx1), "=l"(wy1) : "r"(qa + 128));
            asm("ld.shared.v2.b64 {%0,%1}, [%2];" : "=l"(wz1), "=l"(bb1) : "r"(qa + 144));

            uint32_t at0[4], at1[4];
            at0[0] = frag_pair(rpx[0], rpy[0], rpz[0], wx0, wy0, wz0, bb0, c055, c045);
            at0[1] = frag_pair(rpx[1], rpy[1], rpz[1], wx0, wy0, wz0, bb0, c055, c045);
            at0[2] = frag_pair(rpx[0], rpy[0], rpz[0], wx1, wy1, wz1, bb1, c055, c045);
            at0[3] = frag_pair(rpx[1], rpy[1], rpz[1], wx1, wy1, wz1, bb1, c055, c045);
            at1[0] = frag_pair(rpx[2], rpy[2], rpz[2], wx0, wy0, wz0, bb0, c055, c045);
            at1[1] = frag_pair(rpx[3], rpy[3], rpz[3], wx0, wy0, wz0, bb0, c055, c045);
            at1[2] = frag_pair(rpx[2], rpy[2], rpz[2], wx1, wy1, wz1, bb1, c055, c045);
            at1[3] = frag_pair(rpx[3], rpy[3], rpz[3], wx1, wy1, wz1, bb1, c055, c045);

            const uint32_t bptr = bfrag_base + (uint32_t)s * 2048u;
#pragma unroll
            for (int ni = 0; ni < 8; ++ni) {
                uint32_t h0, h1;
                asm volatile("ld.shared.v2.u32 {%0,%1}, [%2];"
                             : "=r"(h0), "=r"(h1) : "r"(bptr + ni * 256u));
                mma_f16(&acc[ni * 8],     at0, h0, h1);
                mma_f16(&acc[ni * 8 + 4], at1, h0, h1);
            }
        }

        // ---- transpose G to fp16x2 Gs16 [32 rows x 144B] ----
        {
            const uint32_t gdst = wbase + (uint32_t)(r * 4 + q * GSTRIDE);
#pragma unroll
            for (int ni = 0; ni < 8; ++ni) {
#pragma unroll
                for (int mi = 0; mi < 2; ++mi) {
                    const float* c = &acc[ni * 8 + mi * 4];
                    const uint32_t u0 = cvt_f16x2_ff(c[0], c[1]);
                    const uint32_t u1 = cvt_f16x2_ff(c[2], c[3]);
                    const uint32_t a = gdst + (uint32_t)(mi * 16 * GSTRIDE + ni * 16);
                    asm volatile("st.shared.b32 [%0], %1;" :: "r"(a), "r"(u0));
                    asm volatile("st.shared.b32 [%0], %1;" :: "r"(a + 8 * GSTRIDE), "r"(u1));
                }
            }
        }
        __syncwarp();

        // ---- epilogue: out[f] = sum_k (G[k,f] + b2[f]) * x_h[j_k, f] ----
        const __half2* xhb = g_xh + (size_t)b * Nc * 32;
        const uint32_t gsrc = wbase + (uint32_t)lane * 4u;
        float o0 = 0.0f, o1 = 0.0f;
#pragma unroll
        for (int kb = 0; kb < 4; ++kb) {
            __half2 xv[8];
#pragma unroll
            for (int u = 0; u < 8; ++u) {
                const int jk = __shfl_sync(0xFFFFFFFFu, j, kb * 8 + u);
                xv[u] = xhb[(size_t)jk * 32 + lane];
            }
#pragma unroll
            for (int u = 0; u < 8; ++u) {
                uint32_t gv;
                asm volatile("ld.shared.b32 %0, [%1];"
                             : "=r"(gv) : "r"(gsrc + (uint32_t)((kb * 8 + u) * GSTRIDE)));
                float g0, g1;
                unpack_h2(gv, g0, g1);
                const float2 xf = __half22float2(xv[u]);
                o0 = fmaf(g0 + b20, xf.x, o0);
                o1 = fmaf(g1 + b21, xf.y, o1);
            }
        }
        __syncwarp();   // Gs region reused next iteration

        *(float2*)(out + (size_t)p * Dc + f0) = make_float2(o0, o1);
    }
}

extern "C" void kernel_launch(void* const* d_in, const int* in_sizes, int n_in,
                              void* d_out, int out_size) {
    const float* x    = (const float*)d_in[0];
    const float* pos  = (const float*)d_in[1];
    const int*   nidx = (const int*)  d_in[2];
    const float* W1   = (const float*)d_in[3];
    const float* b1   = (const float*)d_in[4];
    const float* W2   = (const float*)d_in[5];
    const float* b2   = (const float*)d_in[6];
    float* out = (float*)d_out;
    (void)in_sizes; (void)n_in; (void)out_size;

    // x -> fp16 scratch (4*16384*64 floats = 2,097,152 half2)
    cvt_x_kernel<<<8192, 256>>>(x);

    cudaFuncSetAttribute(pc_mma_kernel, cudaFuncAttributeMaxDynamicSharedMemorySize,
                         SMEM_BYTES);
    pc_mma_kernel<<<NCTA, NTHR, SMEM_BYTES>>>(pos, nidx, W1, b1, W2, b2, out);
}

// round 11
// speedup vs baseline: 1.9122x; 1.0351x over previous
#include <cuda_runtime.h>
#include <cuda_fp16.h>
#include <cstdint>
#include <cstddef>

namespace {

constexpr int Nc = 16384, Kc = 32, Dc = 64;
constexpr int POINTS = 4 * Nc;           // 65536
constexpr int NTHR   = 128;              // 4 warps / CTA
constexpr int NCTA   = 444;              // 3 CTAs / SM

// ---- shared memory layout (byte offsets) ----
constexpr int SM_BFRAG = 0;              // W2 fp16 fragment table: 4*8*32*8 = 8192 B
constexpr int SM_W1Q   = 8192;           // packed W1/b1 col-pair table: 32*32 = 1024 B
constexpr int SM_WARP  = 9216;           // 4 per-warp Gs16 regions
constexpr int PW       = 4608;           // Gs16 [32 x 144B]
constexpr int SMEM_BYTES = SM_WARP + 4 * PW;   // 27648
constexpr int GSTRIDE = 144;

__device__ __forceinline__ uint32_t smem_u32(const void* p) {
    uint32_t a;
    asm("{ .reg .u64 t; cvta.to.shared.u64 t, %1; cvt.u32.u64 %0, t; }" : "=r"(a) : "l"(p));
    return a;
}
__device__ __forceinline__ uint32_t pack_h2(__half lo, __half hi) {
    return (uint32_t)__half_as_ushort(lo) | ((uint32_t)__half_as_ushort(hi) << 16);
}
__device__ __forceinline__ unsigned long long pack_f2(float lo, float hi) {
    unsigned long long d;
    asm("mov.b64 %0, {%1, %2};" : "=l"(d) : "f"(lo), "f"(hi));
    return d;
}
__device__ __forceinline__ unsigned long long ffma2(unsigned long long a,
                                                    unsigned long long b,
                                                    unsigned long long c) {
    unsigned long long d;
    asm("fma.rn.f32x2 %0, %1, %2, %3;" : "=l"(d) : "l"(a), "l"(b), "l"(c));
    return d;
}
__device__ __forceinline__ unsigned long long fmul2(unsigned long long a,
                                                    unsigned long long b) {
    unsigned long long d;
    asm("mul.rn.f32x2 %0, %1, %2;" : "=l"(d) : "l"(a), "l"(b));
    return d;
}
__device__ __forceinline__ uint32_t cvt_f16x2(unsigned long long zpair) {
    uint32_t lo, hi, d;
    asm("mov.b64 {%0, %1}, %2;" : "=r"(lo), "=r"(hi) : "l"(zpair));
    asm("cvt.rn.f16x2.f32 %0, %1, %2;" : "=r"(d)
        : "f"(__uint_as_float(hi)), "f"(__uint_as_float(lo)));
    return d;
}
__device__ __forceinline__ uint32_t cvt_f16x2_ff(float a, float b) {
    uint32_t d;
    asm("cvt.rn.f16x2.f32 %0, %1, %2;" : "=r"(d) : "f"(b), "f"(a));
    return d;
}
__device__ __forceinline__ unsigned long long abs2(unsigned long long a) {
    uint32_t lo, hi;
    asm("mov.b64 {%0, %1}, %2;" : "=r"(lo), "=r"(hi) : "l"(a));
    lo &= 0x7FFFFFFFu; hi &= 0x7FFFFFFFu;
    unsigned long long d;
    asm("mov.b64 %0, {%1, %2};" : "=l"(d) : "r"(lo), "r"(hi));
    return d;
}
__device__ __forceinline__ void mma_f16(float* c, const uint32_t* a,
                                        uint32_t b0, uint32_t b1) {
    asm volatile(
        "mma.sync.aligned.m16n8k16.row.col.f32.f16.f16.f32 "
        "{%0,%1,%2,%3}, {%4,%5,%6,%7}, {%8,%9}, {%0,%1,%2,%3};"
        : "+f"(c[0]), "+f"(c[1]), "+f"(c[2]), "+f"(c[3])
        : "r"(a[0]), "r"(a[1]), "r"(a[2]), "r"(a[3]), "r"(b0), "r"(b1));
}
// one fragment reg: fp16x2 of leaky(rel . W1[:,c0..c0+1] + b1) for one row
__device__ __forceinline__ uint32_t frag_pair(
    unsigned long long rpx, unsigned long long rpy, unsigned long long rpz,
    unsigned long long wx, unsigned long long wy, unsigned long long wz,
    unsigned long long bb,
    unsigned long long c055, unsigned long long c045) {
    unsigned long long z = ffma2(rpx, wx, ffma2(rpy, wy, ffma2(rpz, wz, bb)));
    z = ffma2(abs2(z), c045, fmul2(z, c055));   // leaky = 0.55 z + 0.45 |z|
    return cvt_f16x2(z);
}

} // namespace

// x pre-converted to fp16 (8 MB static scratch; written by cvt_x_kernel)
__device__ __half2 g_xh[(size_t)4 * 16384 * 32];

__global__ void cvt_x_kernel(const float* __restrict__ x) {
    const int i = blockIdx.x * blockDim.x + threadIdx.x;   // 2,097,152 threads
    const float2 v = ((const float2*)x)[i];
    g_xh[i] = __floats2half2_rn(v.x, v.y);
}

__global__ void __launch_bounds__(NTHR, 3) pc_mma_kernel(
    const float* __restrict__ pos,    // [B, N, 3]
    const int*   __restrict__ nidx,   // [B, N, 32]
    const float* __restrict__ W1,     // [3, 64]
    const float* __restrict__ b1,     // [64]
    const float* __restrict__ W2,     // [64, 64]
    const float* __restrict__ b2,     // [64]
    float*       __restrict__ out)    // [B, N, 64]
{
    extern __shared__ char smem[];
    const uint32_t sb = smem_u32(smem);

    const int tid  = threadIdx.x;
    const int warp = tid >> 5;
    const int lane = tid & 31;
    const int f0   = 2 * lane;
    const int q    = lane >> 2;       // fragment row base
    const int r    = lane & 3;        // fragment col-pair selector

    // ================= one-time init =================
    // W2'' fp16 fragment table (single plane), entry (s, ni, ln) = 8B {b0, b1}
    for (int i = tid; i < 4 * 8 * 32; i += NTHR) {
        const int s = i >> 8, ni = (i >> 5) & 7, ln = i & 31;
        const int n  = ni * 8 + (ln >> 2);
        const int k0 = s * 16 + (ln & 3) * 2;
        uint2 e;
        e.x = pack_h2(__float2half_rn(W2[k0 * Dc + n]),
                      __float2half_rn(W2[(k0 + 1) * Dc + n]));
        e.y = pack_h2(__float2half_rn(W2[(k0 + 8) * Dc + n]),
                      __float2half_rn(W2[(k0 + 9) * Dc + n]));
        *(uint2*)(smem + SM_BFRAG + (size_t)i * 8) = e;
    }
    // W1/b1 col-pair table: entry e = (s*2+d)*4 + r, 32B:
    //   {W1[0][c0],W1[0][c0+1]} {W1[1][..]} {W1[2][..]} {b1[..]},  c0=16s+2r+8d
    for (int e = tid; e < 32; e += NTHR) {
        const int er = e & 3, ed = (e >> 2) & 1, es = e >> 3;
        const int c0 = 16 * es + 2 * er + 8 * ed;
        float2* dst = (float2*)(smem + SM_W1Q + (size_t)e * 32);
        dst[0] = make_float2(W1[c0],          W1[c0 + 1]);
        dst[1] = make_float2(W1[Dc + c0],     W1[Dc + c0 + 1]);
        dst[2] = make_float2(W1[2 * Dc + c0], W1[2 * Dc + c0 + 1]);
        dst[3] = make_float2(b1[c0],          b1[c0 + 1]);
    }
    __syncthreads();

    // ================= per-lane constants =================
    // b2 in fragment layout: cols (ni*8 + 2r, +1) for ni = 0..7
    float2 b2f[8];
#pragma unroll
    for (int ni = 0; ni < 8; ++ni)
        b2f[ni] = *(const float2*)(b2 + ni * 8 + 2 * r);

    const uint32_t wbase = sb + SM_WARP + warp * PW;          // Gs16 region
    const uint32_t bfrag_base = sb + SM_BFRAG + (uint32_t)lane * 8u;
    const uint32_t w1q_base = sb + SM_W1Q + (uint32_t)r * 32u;

    const unsigned long long c055 = pack_f2(0.55f, 0.55f);
    const unsigned long long c045 = pack_f2(0.45f, 0.45f);

    const int pstride = NCTA * 4;

    // ---- prefetch state for point p ----
    int p = blockIdx.x * 4 + warp;
    int   jv = 0;
    float cxv = 0.f, cyv = 0.f, czv = 0.f, nxv = 0.f, nyv = 0.f, nzv = 0.f;
    if (p < POINTS) {
        const int bb = p >> 14;
        jv  = nidx[(size_t)p * Kc + lane];
        cxv = pos[(size_t)p * 3 + 0];
        cyv = pos[(size_t)p * 3 + 1];
        czv = pos[(size_t)p * 3 + 2];
        const float* npp = pos + (size_t)(bb * Nc + jv) * 3;
        nxv = npp[0]; nyv = npp[1]; nzv = npp[2];
    }

    for (; p < POINTS; p += pstride) {
        const int b = p >> 14;
        const int j = jv;
        const float rx = cxv - nxv, ry = cyv - nyv, rz = czv - nzv;

        // ---- rel for this lane's 4 fragment rows (q, q+8, q+16, q+24) ----
        unsigned long long rpx[4], rpy[4], rpz[4];
#pragma unroll
        for (int i = 0; i < 4; ++i) {
            const int src = q + 8 * i;
            const float vx = __shfl_sync(0xFFFFFFFFu, rx, src);
            const float vy = __shfl_sync(0xFFFFFFFFu, ry, src);
            const float vz = __shfl_sync(0xFFFFFFFFu, rz, src);
            rpx[i] = pack_f2(vx, vx);
            rpy[i] = pack_f2(vy, vy);
            rpz[i] = pack_f2(vz, vz);
        }

        // ---- prefetch next point's idx/pos (consumed next iteration) ----
        {
            const int pn = p + pstride;
            if (pn < POINTS) {
                const int bn = pn >> 14;
                jv  = nidx[(size_t)pn * Kc + lane];
                cxv = pos[(size_t)pn * 3 + 0];
                cyv = pos[(size_t)pn * 3 + 1];
                czv = pos[(size_t)pn * 3 + 2];
                const float* npp = pos + (size_t)(bn * Nc + jv) * 3;
                nxv = npp[0]; nyv = npp[1]; nzv = npp[2];
            }
        }

        // ---- GEMM, acc initialized with b2 (G' = H*W2 + b2 from the MMA) ----
        float acc[64];
#pragma unroll
        for (int ni = 0; ni < 8; ++ni) {
            acc[ni * 8 + 0] = b2f[ni].x; acc[ni * 8 + 1] = b2f[ni].y;
            acc[ni * 8 + 2] = b2f[ni].x; acc[ni * 8 + 3] = b2f[ni].y;
            acc[ni * 8 + 4] = b2f[ni].x; acc[ni * 8 + 5] = b2f[ni].y;
            acc[ni * 8 + 6] = b2f[ni].x; acc[ni * 8 + 7] = b2f[ni].y;
        }

#pragma unroll
        for (int s = 0; s < 4; ++s) {
            unsigned long long wx0, wy0, wz0, bb0, wx1, wy1, wz1, bb1;
            const uint32_t qa = w1q_base + (uint32_t)(s * 256);
            asm("ld.shared.v2.b64 {%0,%1}, [%2];" : "=l"(wx0), "=l"(wy0) : "r"(qa));
            asm("ld.shared.v2.b64 {%0,%1}, [%2];" : "=l"(wz0), "=l"(bb0) : "r"(qa + 16));
            asm("ld.shared.v2.b64 {%0,%1}, [%2];" : "=l"(wx1), "=l"(wy1) : "r"(qa + 128));
            asm("ld.shared.v2.b64 {%0,%1}, [%2];" : "=l"(wz1), "=l"(bb1) : "r"(qa + 144));

            uint32_t at0[4], at1[4];
            at0[0] = frag_pair(rpx[0], rpy[0], rpz[0], wx0, wy0, wz0, bb0, c055, c045);
            at0[1] = frag_pair(rpx[1], rpy[1], rpz[1], wx0, wy0, wz0, bb0, c055, c045);
            at0[2] = frag_pair(rpx[0], rpy[0], rpz[0], wx1, wy1, wz1, bb1, c055, c045);
            at0[3] = frag_pair(rpx[1], rpy[1], rpz[1], wx1, wy1, wz1, bb1, c055, c045);
            at1[0] = frag_pair(rpx[2], rpy[2], rpz[2], wx0, wy0, wz0, bb0, c055, c045);
            at1[1] = frag_pair(rpx[3], rpy[3], rpz[3], wx0, wy0, wz0, bb0, c055, c045);
            at1[2] = frag_pair(rpx[2], rpy[2], rpz[2], wx1, wy1, wz1, bb1, c055, c045);
            at1[3] = frag_pair(rpx[3], rpy[3], rpz[3], wx1, wy1, wz1, bb1, c055, c045);

            const uint32_t bptr = bfrag_base + (uint32_t)s * 2048u;
#pragma unroll
            for (int ni = 0; ni < 8; ++ni) {
                uint32_t h0, h1;
                asm volatile("ld.shared.v2.u32 {%0,%1}, [%2];"
                             : "=r"(h0), "=r"(h1) : "r"(bptr + ni * 256u));
                mma_f16(&acc[ni * 8],     at0, h0, h1);
                mma_f16(&acc[ni * 8 + 4], at1, h0, h1);
            }
        }

        // ---- transpose G' to fp16x2 Gs16 [32 rows x 144B] ----
        {
            const uint32_t gdst = wbase + (uint32_t)(r * 4 + q * GSTRIDE);
#pragma unroll
            for (int ni = 0; ni < 8; ++ni) {
#pragma unroll
                for (int mi = 0; mi < 2; ++mi) {
                    const float* c = &acc[ni * 8 + mi * 4];
                    const uint32_t u0 = cvt_f16x2_ff(c[0], c[1]);
                    const uint32_t u1 = cvt_f16x2_ff(c[2], c[3]);
                    const uint32_t a = gdst + (uint32_t)(mi * 16 * GSTRIDE + ni * 16);
                    asm volatile("st.shared.b32 [%0], %1;" :: "r"(a), "r"(u0));
                    asm volatile("st.shared.b32 [%0], %1;" :: "r"(a + 8 * GSTRIDE), "r"(u1));
                }
            }
        }
        __syncwarp();

        // ---- epilogue: out[f] = sum_k G'[k,f] * x_h[j_k, f]  (fp16 product) ----
        const __half2* xhb = g_xh + (size_t)b * Nc * 32;
        const uint32_t gsrc = wbase + (uint32_t)lane * 4u;
        float o0 = 0.0f, o1 = 0.0f;
#pragma unroll
        for (int kb = 0; kb < 4; ++kb) {
            __half2 xv[8];
#pragma unroll
            for (int u = 0; u < 8; ++u) {
                const int jk = __shfl_sync(0xFFFFFFFFu, j, kb * 8 + u);
                xv[u] = xhb[(size_t)jk * 32 + lane];
            }
#pragma unroll
            for (int u = 0; u < 8; ++u) {
                uint32_t gv;
                asm volatile("ld.shared.b32 %0, [%1];"
                             : "=r"(gv) : "r"(gsrc + (uint32_t)((kb * 8 + u) * GSTRIDE)));
                const __half2 prod = __hmul2(*(const __half2*)&gv, xv[u]);
                const float2 pf = __half22float2(prod);
                o0 += pf.x;
                o1 += pf.y;
            }
        }
        __syncwarp();   // Gs region reused next iteration

        *(float2*)(out + (size_t)p * Dc + f0) = make_float2(o0, o1);
    }
}

extern "C" void kernel_launch(void* const* d_in, const int* in_sizes, int n_in,
                              void* d_out, int out_size) {
    const float* x    = (const float*)d_in[0];
    const float* pos  = (const float*)d_in[1];
    const int*   nidx = (const int*)  d_in[2];
    const float* W1   = (const float*)d_in[3];
    const float* b1   = (const float*)d_in[4];
    const float* W2   = (const float*)d_in[5];
    const float* b2   = (const float*)d_in[6];
    float* out = (float*)d_out;
    (void)in_sizes; (void)n_in; (void)out_size;

    // x -> fp16 scratch (4*16384*64 floats = 2,097,152 half2)
    cvt_x_kernel<<<8192, 256>>>(x);

    cudaFuncSetAttribute(pc_mma_kernel, cudaFuncAttributeMaxDynamicSharedMemorySize,
                         SMEM_BYTES);
    pc_mma_kernel<<<NCTA, NTHR, SMEM_BYTES>>>(pos, nidx, W1, b1, W2, b2, out);
}

// round 12
// speedup vs baseline: 2.0267x; 1.0599x over previous
#include <cuda_runtime.h>
#include <cuda_fp16.h>
#include <cstdint>
#include <cstddef>

namespace {

constexpr int Nc = 16384, Kc = 32, Dc = 64;
constexpr int POINTS = 4 * Nc;           // 65536
constexpr int NTHR   = 128;              // 4 warps / CTA
constexpr int NCTA   = 592;              // 4 CTAs / SM

// ---- shared memory layout (byte offsets) ----
constexpr int SM_BFRAG = 0;              // W2 fp16 fragment table: 4*8*32*8 = 8192 B
constexpr int SM_W1Q   = 8192;           // packed W1/b1 col-pair table: 32*32 = 1024 B
constexpr int SM_WARP  = 9216;           // 4 per-warp Gs16 regions
constexpr int PW       = 4608;           // Gs16 [32 x 144B]
constexpr int SMEM_BYTES = SM_WARP + 4 * PW;   // 27648
constexpr int GSTRIDE = 144;

__device__ __forceinline__ uint32_t smem_u32(const void* p) {
    uint32_t a;
    asm("{ .reg .u64 t; cvta.to.shared.u64 t, %1; cvt.u32.u64 %0, t; }" : "=r"(a) : "l"(p));
    return a;
}
__device__ __forceinline__ uint32_t pack_h2(__half lo, __half hi) {
    return (uint32_t)__half_as_ushort(lo) | ((uint32_t)__half_as_ushort(hi) << 16);
}
__device__ __forceinline__ unsigned long long pack_f2(float lo, float hi) {
    unsigned long long d;
    asm("mov.b64 %0, {%1, %2};" : "=l"(d) : "f"(lo), "f"(hi));
    return d;
}
__device__ __forceinline__ unsigned long long ffma2(unsigned long long a,
                                                    unsigned long long b,
                                                    unsigned long long c) {
    unsigned long long d;
    asm("fma.rn.f32x2 %0, %1, %2, %3;" : "=l"(d) : "l"(a), "l"(b), "l"(c));
    return d;
}
__device__ __forceinline__ unsigned long long fmul2(unsigned long long a,
                                                    unsigned long long b) {
    unsigned long long d;
    asm("mul.rn.f32x2 %0, %1, %2;" : "=l"(d) : "l"(a), "l"(b));
    return d;
}
__device__ __forceinline__ uint32_t cvt_f16x2(unsigned long long zpair) {
    uint32_t lo, hi, d;
    asm("mov.b64 {%0, %1}, %2;" : "=r"(lo), "=r"(hi) : "l"(zpair));
    asm("cvt.rn.f16x2.f32 %0, %1, %2;" : "=r"(d)
        : "f"(__uint_as_float(hi)), "f"(__uint_as_float(lo)));
    return d;
}
__device__ __forceinline__ unsigned long long abs2(unsigned long long a) {
    uint32_t lo, hi;
    asm("mov.b64 {%0, %1}, %2;" : "=r"(lo), "=r"(hi) : "l"(a));
    lo &= 0x7FFFFFFFu; hi &= 0x7FFFFFFFu;
    unsigned long long d;
    asm("mov.b64 %0, {%1, %2};" : "=l"(d) : "r"(lo), "r"(hi));
    return d;
}
// fp16-accumulate HMMA: C/D fragment = 2 regs of fp16x2
__device__ __forceinline__ void mma_f16_h(uint32_t* c, const uint32_t* a,
                                          uint32_t b0, uint32_t b1) {
    asm volatile(
        "mma.sync.aligned.m16n8k16.row.col.f16.f16.f16.f16 "
        "{%0,%1}, {%2,%3,%4,%5}, {%6,%7}, {%0,%1};"
        : "+r"(c[0]), "+r"(c[1])
        : "r"(a[0]), "r"(a[1]), "r"(a[2]), "r"(a[3]), "r"(b0), "r"(b1));
}
// one fragment reg: fp16x2 of leaky(rel . W1[:,c0..c0+1] + b1) for one row
__device__ __forceinline__ uint32_t frag_pair(
    unsigned long long rpx, unsigned long long rpy, unsigned long long rpz,
    unsigned long long wx, unsigned long long wy, unsigned long long wz,
    unsigned long long bb,
    unsigned long long c055, unsigned long long c045) {
    unsigned long long z = ffma2(rpx, wx, ffma2(rpy, wy, ffma2(rpz, wz, bb)));
    z = ffma2(abs2(z), c045, fmul2(z, c055));   // leaky = 0.55 z + 0.45 |z|
    return cvt_f16x2(z);
}

} // namespace

// x pre-converted to fp16 (8 MB static scratch; written by cvt_x_kernel)
__device__ __half2 g_xh[(size_t)4 * 16384 * 32];

__global__ void cvt_x_kernel(const float* __restrict__ x) {
    const int i = blockIdx.x * blockDim.x + threadIdx.x;   // 2,097,152 threads
    const float2 v = ((const float2*)x)[i];
    g_xh[i] = __floats2half2_rn(v.x, v.y);
}

__global__ void __launch_bounds__(NTHR, 4) pc_mma_kernel(
    const float* __restrict__ pos,    // [B, N, 3]
    const int*   __restrict__ nidx,   // [B, N, 32]
    const float* __restrict__ W1,     // [3, 64]
    const float* __restrict__ b1,     // [64]
    const float* __restrict__ W2,     // [64, 64]
    const float* __restrict__ b2,     // [64]
    float*       __restrict__ out)    // [B, N, 64]
{
    extern __shared__ char smem[];
    const uint32_t sb = smem_u32(smem);

    const int tid  = threadIdx.x;
    const int warp = tid >> 5;
    const int lane = tid & 31;
    const int f0   = 2 * lane;
    const int q    = lane >> 2;       // fragment row base
    const int r    = lane & 3;        // fragment col-pair selector

    // ================= one-time init =================
    // W2'' fp16 fragment table (single plane), entry (s, ni, ln) = 8B {b0, b1}
    for (int i = tid; i < 4 * 8 * 32; i += NTHR) {
        const int s = i >> 8, ni = (i >> 5) & 7, ln = i & 31;
        const int n  = ni * 8 + (ln >> 2);
        const int k0 = s * 16 + (ln & 3) * 2;
        uint2 e;
        e.x = pack_h2(__float2half_rn(W2[k0 * Dc + n]),
                      __float2half_rn(W2[(k0 + 1) * Dc + n]));
        e.y = pack_h2(__float2half_rn(W2[(k0 + 8) * Dc + n]),
                      __float2half_rn(W2[(k0 + 9) * Dc + n]));
        *(uint2*)(smem + SM_BFRAG + (size_t)i * 8) = e;
    }
    // W1/b1 col-pair table: entry e = (s*2+d)*4 + r, 32B:
    //   {W1[0][c0],W1[0][c0+1]} {W1[1][..]} {W1[2][..]} {b1[..]},  c0=16s+2r+8d
    for (int e = tid; e < 32; e += NTHR) {
        const int er = e & 3, ed = (e >> 2) & 1, es = e >> 3;
        const int c0 = 16 * es + 2 * er + 8 * ed;
        float2* dst = (float2*)(smem + SM_W1Q + (size_t)e * 32);
        dst[0] = make_float2(W1[c0],          W1[c0 + 1]);
        dst[1] = make_float2(W1[Dc + c0],     W1[Dc + c0 + 1]);
        dst[2] = make_float2(W1[2 * Dc + c0], W1[2 * Dc + c0 + 1]);
        dst[3] = make_float2(b1[c0],          b1[c0 + 1]);
    }
    __syncthreads();

    // ================= per-lane constants =================
    // b2 in fragment layout, packed fp16x2: cols (ni*8 + 2r, +1)
    uint32_t b2h[8];
#pragma unroll
    for (int ni = 0; ni < 8; ++ni)
        b2h[ni] = pack_h2(__float2half_rn(b2[ni * 8 + 2 * r]),
                          __float2half_rn(b2[ni * 8 + 2 * r + 1]));

    const uint32_t wbase = sb + SM_WARP + warp * PW;          // Gs16 region
    const uint32_t bfrag_base = sb + SM_BFRAG + (uint32_t)lane * 8u;
    const uint32_t w1q_base = sb + SM_W1Q + (uint32_t)r * 32u;

    const unsigned long long c055 = pack_f2(0.55f, 0.55f);
    const unsigned long long c045 = pack_f2(0.45f, 0.45f);

    const int pstride = NCTA * 4;

    // ---- prefetch state for point p ----
    int p = blockIdx.x * 4 + warp;
    int   jv = 0;
    float cxv = 0.f, cyv = 0.f, czv = 0.f, nxv = 0.f, nyv = 0.f, nzv = 0.f;
    if (p < POINTS) {
        const int bb = p >> 14;
        jv  = nidx[(size_t)p * Kc + lane];
        cxv = pos[(size_t)p * 3 + 0];
        cyv = pos[(size_t)p * 3 + 1];
        czv = pos[(size_t)p * 3 + 2];
        const float* npp = pos + (size_t)(bb * Nc + jv) * 3;
        nxv = npp[0]; nyv = npp[1]; nzv = npp[2];
    }

    for (; p < POINTS; p += pstride) {
        const int b = p >> 14;
        const int j = jv;
        const float rx = cxv - nxv, ry = cyv - nyv, rz = czv - nzv;

        // ---- rel for this lane's 4 fragment rows (q, q+8, q+16, q+24) ----
        unsigned long long rpx[4], rpy[4], rpz[4];
#pragma unroll
        for (int i = 0; i < 4; ++i) {
            const int src = q + 8 * i;
            const float vx = __shfl_sync(0xFFFFFFFFu, rx, src);
            const float vy = __shfl_sync(0xFFFFFFFFu, ry, src);
            const float vz = __shfl_sync(0xFFFFFFFFu, rz, src);
            rpx[i] = pack_f2(vx, vx);
            rpy[i] = pack_f2(vy, vy);
            rpz[i] = pack_f2(vz, vz);
        }

        // ---- prefetch next point's idx/pos (consumed next iteration) ----
        {
            const int pn = p + pstride;
            if (pn < POINTS) {
                const int bn = pn >> 14;
                jv  = nidx[(size_t)pn * Kc + lane];
                cxv = pos[(size_t)pn * 3 + 0];
                cyv = pos[(size_t)pn * 3 + 1];
                czv = pos[(size_t)pn * 3 + 2];
                const float* npp = pos + (size_t)(bn * Nc + jv) * 3;
                nxv = npp[0]; nyv = npp[1]; nzv = npp[2];
            }
        }

        // ---- GEMM (fp16 acc), acc init = b2 -> G' = H*W2 + b2 in fp16x2 ----
        // acc[ni*4 + 0..1] = rows {q, q+8} (mma on at0)
        // acc[ni*4 + 2..3] = rows {q+16, q+24} (mma on at1)
        uint32_t acc[32];
#pragma unroll
        for (int ni = 0; ni < 8; ++ni) {
            acc[ni * 4 + 0] = b2h[ni];
            acc[ni * 4 + 1] = b2h[ni];
            acc[ni * 4 + 2] = b2h[ni];
            acc[ni * 4 + 3] = b2h[ni];
        }

#pragma unroll
        for (int s = 0; s < 4; ++s) {
            unsigned long long wx0, wy0, wz0, bb0, wx1, wy1, wz1, bb1;
            const uint32_t qa = w1q_base + (uint32_t)(s * 256);
            asm("ld.shared.v2.b64 {%0,%1}, [%2];" : "=l"(wx0), "=l"(wy0) : "r"(qa));
            asm("ld.shared.v2.b64 {%0,%1}, [%2];" : "=l"(wz0), "=l"(bb0) : "r"(qa + 16));
            asm("ld.shared.v2.b64 {%0,%1}, [%2];" : "=l"(wx1), "=l"(wy1) : "r"(qa + 128));
            asm("ld.shared.v2.b64 {%0,%1}, [%2];" : "=l"(wz1), "=l"(bb1) : "r"(qa + 144));

            uint32_t at0[4], at1[4];
            at0[0] = frag_pair(rpx[0], rpy[0], rpz[0], wx0, wy0, wz0, bb0, c055, c045);
            at0[1] = frag_pair(rpx[1], rpy[1], rpz[1], wx0, wy0, wz0, bb0, c055, c045);
            at0[2] = frag_pair(rpx[0], rpy[0], rpz[0], wx1, wy1, wz1, bb1, c055, c045);
            at0[3] = frag_pair(rpx[1], rpy[1], rpz[1], wx1, wy1, wz1, bb1, c055, c045);
            at1[0] = frag_pair(rpx[2], rpy[2], rpz[2], wx0, wy0, wz0, bb0, c055, c045);
            at1[1] = frag_pair(rpx[3], rpy[3], rpz[3], wx0, wy0, wz0, bb0, c055, c045);
            at1[2] = frag_pair(rpx[2], rpy[2], rpz[2], wx1, wy1, wz1, bb1, c055, c045);
            at1[3] = frag_pair(rpx[3], rpy[3], rpz[3], wx1, wy1, wz1, bb1, c055, c045);

            const uint32_t bptr = bfrag_base + (uint32_t)s * 2048u;
#pragma unroll
            for (int ni = 0; ni < 8; ++ni) {
                uint32_t h0, h1;
                asm volatile("ld.shared.v2.u32 {%0,%1}, [%2];"
                             : "=r"(h0), "=r"(h1) : "r"(bptr + ni * 256u));
                mma_f16_h(&acc[ni * 4],     at0, h0, h1);
                mma_f16_h(&acc[ni * 4 + 2], at1, h0, h1);
            }
        }

        // ---- transpose G' to Gs16 [32 rows x 144B] (regs already fp16x2) ----
        {
            const uint32_t gdst = wbase + (uint32_t)(r * 4 + q * GSTRIDE);
#pragma unroll
            for (int ni = 0; ni < 8; ++ni) {
                const uint32_t a = gdst + (uint32_t)(ni * 16);
                asm volatile("st.shared.b32 [%0], %1;" :: "r"(a),                 "r"(acc[ni * 4 + 0]));
                asm volatile("st.shared.b32 [%0], %1;" :: "r"(a + 8 * GSTRIDE),   "r"(acc[ni * 4 + 1]));
                asm volatile("st.shared.b32 [%0], %1;" :: "r"(a + 16 * GSTRIDE),  "r"(acc[ni * 4 + 2]));
                asm volatile("st.shared.b32 [%0], %1;" :: "r"(a + 24 * GSTRIDE),  "r"(acc[ni * 4 + 3]));
            }
        }
        __syncwarp();

        // ---- epilogue: out[f] = sum_k G'[k,f] * x_h[j_k, f]  (fp16 product) ----
        const __half2* xhb = g_xh + (size_t)b * Nc * 32;
        const uint32_t gsrc = wbase + (uint32_t)lane * 4u;
        float o0 = 0.0f, o1 = 0.0f;
#pragma unroll
        for (int kb = 0; kb < 4; ++kb) {
            __half2 xv[8];
#pragma unroll
            for (int u = 0; u < 8; ++u) {
                const int jk = __shfl_sync(0xFFFFFFFFu, j, kb * 8 + u);
                xv[u] = xhb[(size_t)jk * 32 + lane];
            }
#pragma unroll
            for (int u = 0; u < 8; ++u) {
                uint32_t gv;
                asm volatile("ld.shared.b32 %0, [%1];"
                             : "=r"(gv) : "r"(gsrc + (uint32_t)((kb * 8 + u) * GSTRIDE)));
                const __half2 prod = __hmul2(*(const __half2*)&gv, xv[u]);
                const float2 pf = __half22float2(prod);
                o0 += pf.x;
                o1 += pf.y;
            }
        }
        __syncwarp();   // Gs region reused next iteration

        *(float2*)(out + (size_t)p * Dc + f0) = make_float2(o0, o1);
    }
}

extern "C" void kernel_launch(void* const* d_in, const int* in_sizes, int n_in,
                              void* d_out, int out_size) {
    const float* x    = (const float*)d_in[0];
    const float* pos  = (const float*)d_in[1];
    const int*   nidx = (const int*)  d_in[2];
    const float* W1   = (const float*)d_in[3];
    const float* b1   = (const float*)d_in[4];
    const float* W2   = (const float*)d_in[5];
    const float* b2   = (const float*)d_in[6];
    float* out = (float*)d_out;
    (void)in_sizes; (void)n_in; (void)out_size;

    // x -> fp16 scratch (4*16384*64 floats = 2,097,152 half2)
    cvt_x_kernel<<<8192, 256>>>(x);

    cudaFuncSetAttribute(pc_mma_kernel, cudaFuncAttributeMaxDynamicSharedMemorySize,
                         SMEM_BYTES);
    pc_mma_kernel<<<NCTA, NTHR, SMEM_BYTES>>>(pos, nidx, W1, b1, W2, b2, out);
}